// round 14
// baseline (speedup 1.0000x reference)
#include <cuda_runtime.h>
#include <cuda_bf16.h>
#include <cstdint>
#include <math.h>

#define B_    16
#define N_    4096
#define CIN   256
#define CH_   256
#define DW    512
#define IN_   128
#define NTILES_TOTAL 512
#define GRID_GEMM 148

// tcgen05 asm only compiles under an 'a'-suffixed target pass.
#if defined(__CUDA_ARCH_FEAT_SM103_ALL) || defined(__CUDA_ARCH_FEAT_SM100_ALL) || defined(__CUDA_ARCH_FEAT_SM101_ALL)
#define USE_TCGEN05 1
#else
#define USE_TCGEN05 0
#endif

// -------------------- device scratch --------------------
__device__ float g_attw[B_ * DW];
// W: 16 pre-swizzled 32KB images (256 rows x 128B, SW128 baked in).
// image j = kb*4 + islo*2 + h.  Row perm: w_conv row d (c=d&255, r=d>>8) ->
// h=c>>7, lrow=(c&127)+r*128.  D col (N=256 MMA for channel-half h) = lrow.
__device__ __nv_bfloat16 g_w3[16 * 256 * 64];
// A staging: per-CTA double-buffered slot images [cta][slot 0/1][kb][hi|lo].
// 148 * 2 * 4 * 32KB = ~38.8MB; written by prep warps, TMA-read back (L2-hot).
__device__ __nv_bfloat16 g_x2[(size_t)GRID_GEMM * 2 * 4 * 16384];

// -------------------- PTX helpers --------------------
__device__ __forceinline__ uint32_t smem_u32(const void* p) {
    uint32_t a;
    asm("{ .reg .u64 t; cvta.to.shared.u64 t, %1; cvt.u32.u64 %0, t; }" : "=r"(a) : "l"(p));
    return a;
}
__device__ __forceinline__ uint32_t elect_one() {
    uint32_t pred;
    asm volatile("{\n\t.reg .pred p;\n\telect.sync _|p, 0xFFFFFFFF;\n\tselp.b32 %0, 1, 0, p;\n\t}" : "=r"(pred));
    return pred;
}
#define TCGEN05_ALLOC(sa, n) \
    asm volatile("tcgen05.alloc.cta_group::1.sync.aligned.shared::cta.b32 [%0], %1;" :: "r"((uint32_t)(sa)), "r"((uint32_t)(n)) : "memory")
#define TCGEN05_DEALLOC(t, n) \
    asm volatile("tcgen05.dealloc.cta_group::1.sync.aligned.b32 %0, %1;" :: "r"(t), "r"((uint32_t)(n)))
#define TCGEN05_RELINQ() \
    asm volatile("tcgen05.relinquish_alloc_permit.cta_group::1.sync.aligned;")
#define TCGEN05_COMMIT(mb) \
    asm volatile("tcgen05.commit.cta_group::1.mbarrier::arrive::one.shared::cluster.b64 [%0];" :: "r"((uint32_t)(mb)) : "memory")
#define TCGEN05_WAIT_LD() asm volatile("tcgen05.wait::ld.sync.aligned;" ::: "memory")
#define TCGEN05_FENCE_AFTER() asm volatile("tcgen05.fence::after_thread_sync;" ::: "memory")
#define MBARRIER_INIT(mb, cnt) \
    asm volatile("mbarrier.init.shared.b64 [%0], %1;" :: "r"((uint32_t)(mb)), "r"((uint32_t)(cnt)) : "memory")
#define MBARRIER_ARRIVE(mb) \
    asm volatile("mbarrier.arrive.shared.b64 _, [%0];" :: "r"((uint32_t)(mb)) : "memory")
#define MBARRIER_EXPECT_TX(mb, bytes) \
    asm volatile("mbarrier.arrive.expect_tx.shared.b64 _, [%0], %1;" :: "r"((uint32_t)(mb)), "r"((uint32_t)(bytes)) : "memory")
#define MBARRIER_WAIT_PARITY(mb, ph) do { \
    uint32_t _m = (uint32_t)(mb), _p = (uint32_t)(ph), _d; \
    asm volatile("{\n\t.reg .pred p;\n\tmbarrier.try_wait.parity.acquire.cta.shared::cta.b64 p, [%1], %2;\n\tselp.b32 %0, 1, 0, p;\n\t}" \
        : "=r"(_d) : "r"(_m), "r"(_p) : "memory"); \
    if (!_d) { \
        asm volatile("{\n\t.reg .pred P1;\n\tWL_%=:\n\tmbarrier.try_wait.parity.acquire.cta.shared::cta.b64 P1, [%0], %1, 0x989680;\n\t@P1 bra.uni WD_%=;\n\tbra.uni WL_%=;\n\tWD_%=:\n\t}" \
            :: "r"(_m), "r"(_p) : "memory"); \
    } \
} while (0)
#define BULK_G2S(dst, src, bytes, mb) \
    asm volatile("cp.async.bulk.shared::cta.global.mbarrier::complete_tx::bytes [%0], [%1], %2, [%3];" \
        :: "r"((uint32_t)(dst)), "l"(src), "r"((uint32_t)(bytes)), "r"((uint32_t)(mb)) : "memory")
#define TCGEN05_LD_X32(r, ta) \
    asm volatile("tcgen05.ld.sync.aligned.32x32b.x32.b32 " \
        "{%0,%1,%2,%3,%4,%5,%6,%7,%8,%9,%10,%11,%12,%13,%14,%15," \
        "%16,%17,%18,%19,%20,%21,%22,%23,%24,%25,%26,%27,%28,%29,%30,%31}, [%32];" \
        : "=r"((r)[0]),"=r"((r)[1]),"=r"((r)[2]),"=r"((r)[3]),"=r"((r)[4]),"=r"((r)[5]),"=r"((r)[6]),"=r"((r)[7]), \
          "=r"((r)[8]),"=r"((r)[9]),"=r"((r)[10]),"=r"((r)[11]),"=r"((r)[12]),"=r"((r)[13]),"=r"((r)[14]),"=r"((r)[15]), \
          "=r"((r)[16]),"=r"((r)[17]),"=r"((r)[18]),"=r"((r)[19]),"=r"((r)[20]),"=r"((r)[21]),"=r"((r)[22]),"=r"((r)[23]), \
          "=r"((r)[24]),"=r"((r)[25]),"=r"((r)[26]),"=r"((r)[27]),"=r"((r)[28]),"=r"((r)[29]),"=r"((r)[30]),"=r"((r)[31]) \
        : "r"(ta))

static constexpr uint64_t SMEM_DESC_BASE_SW128 =
    (uint64_t(2) << 61) | (uint64_t(1) << 46) | (uint64_t(64) << 32) | (uint64_t(1) << 16);
#define MAKE_SMEM_DESC(a) (SMEM_DESC_BASE_SW128 | ((uint64_t)((a) >> 4) & 0x3FFF))

#if USE_TCGEN05
// SS-mode cg1 bf16 MMA: D[128,256] += A[128,16] * B[256,16]^T
__device__ __forceinline__ void mma_f16_ss(uint32_t d, uint64_t ad, uint64_t bd, uint32_t idesc, bool acc) {
    uint32_t en = acc ? 1u : 0u;
    asm volatile(
        "{\n\t.reg .pred p;\n\tsetp.ne.u32 p, %5, 0;\n\t"
        "tcgen05.mma.cta_group::1.kind::f16 [%0], %1, %2, %3, {%4, %4, %4, %4}, p;\n\t}"
        :: "r"(d), "l"(ad), "l"(bd), "r"(idesc), "r"(0u), "r"(en) : "memory");
}
#endif
// idesc: F32 accum, BF16 x BF16, M=128, N=256
static constexpr uint32_t IDESC =
    (1u << 4) | (1u << 7) | (1u << 10) | ((256u / 8u) << 17) | ((128u / 16u) << 24);

// fp32 -> bf16 hi/lo split, packed pairs
__device__ __forceinline__ void split4(const float4 v, uint32_t& h01, uint32_t& h23,
                                       uint32_t& l01, uint32_t& l23) {
    __nv_bfloat162 h0 = __floats2bfloat162_rn(v.x, v.y);
    __nv_bfloat162 h1 = __floats2bfloat162_rn(v.z, v.w);
    __nv_bfloat162 l0 = __floats2bfloat162_rn(v.x - __bfloat162float(h0.x),
                                              v.y - __bfloat162float(h0.y));
    __nv_bfloat162 l1 = __floats2bfloat162_rn(v.z - __bfloat162float(h1.x),
                                              v.w - __bfloat162float(h1.y));
    h01 = *(uint32_t*)&h0; h23 = *(uint32_t*)&h1;
    l01 = *(uint32_t*)&l0; l23 = *(uint32_t*)&l1;
}

// ---------------------------------------------------------------------------
// Setup (single launch, 144 blocks): blocks 0..15 attention chain (conv
// inline; only rows n=0/n=1024 survive the rSoftMax slice; b_fc2 cancels);
// blocks 16..143 prep_w (pre-swizzled W images).
// ---------------------------------------------------------------------------
__global__ __launch_bounds__(256) void setup_kernel(
    const float* __restrict__ x,
    const float* __restrict__ w_conv,
    const float* __restrict__ b_conv,
    const float* __restrict__ w_fc1,
    const float* __restrict__ b_fc1,
    const float* __restrict__ w_fc2)
{
    const int tid = threadIdx.x;

    if (blockIdx.x >= 16) {
        const int gi = ((blockIdx.x - 16) * 256 + tid) * 4;
        float4 v = *(const float4*)(w_conv + gi);
        const int d = gi >> 8, k = gi & 255;
        uint32_t h01, h23, l01, l23;
        split4(v, h01, h23, l01, l23);
        const int c = d & 255, r = d >> 8;
        const int nh = c >> 7;
        const int lrow = (c & 127) + (r << 7);
        const int kb = k >> 6, kc = k & 63;
        const uint32_t off = (uint32_t)lrow * 128 + (((uint32_t)kc * 2) ^ ((uint32_t)(lrow & 7) << 4));
        char* basehi = (char*)g_w3 + (size_t)(kb * 4 + nh) * 32768 + off;
        char* baselo = (char*)g_w3 + (size_t)(kb * 4 + 2 + nh) * 32768 + off;
        *(uint2*)basehi = make_uint2(h01, h23);
        *(uint2*)baselo = make_uint2(l01, l23);
        return;
    }

    const int b = blockIdx.x;
    __shared__ float xs0[CIN], xs1[CIN];
    __shared__ float h0[DW], h1[DW];
    __shared__ float gap0[CH_], gap1[CH_];
    __shared__ float g0[IN_], g1[IN_], gd[IN_];

    xs0[tid] = x[(b * N_ + 0)    * CIN + tid];
    xs1[tid] = x[(b * N_ + 1024) * CIN + tid];
    __syncthreads();

    #pragma unroll
    for (int dd = 0; dd < 2; dd++) {
        const int d = tid + dd * 256;
        const float4* w = (const float4*)(w_conv + d * CIN);
        float s0 = 0.f, s1 = 0.f;
        #pragma unroll 8
        for (int k4 = 0; k4 < CIN / 4; k4++) {
            float4 wv = w[k4];
            float4 x0 = ((const float4*)xs0)[k4];
            float4 x1 = ((const float4*)xs1)[k4];
            s0 += wv.x * x0.x + wv.y * x0.y + wv.z * x0.z + wv.w * x0.w;
            s1 += wv.x * x1.x + wv.y * x1.y + wv.z * x1.z + wv.w * x1.w;
        }
        const float bb = b_conv[d];
        h0[d] = fmaxf(s0 + bb, 0.f);
        h1[d] = fmaxf(s1 + bb, 0.f);
    }
    __syncthreads();

    gap0[tid] = h0[tid] + h0[tid + CH_];
    gap1[tid] = h1[tid] + h1[tid + CH_];
    __syncthreads();

    {
        const int i = tid & 127;
        const float* gp = (tid < 128) ? gap0 : gap1;
        const float4* w = (const float4*)(w_fc1 + i * CH_);
        float s = 0.f;
        #pragma unroll 8
        for (int k4 = 0; k4 < CH_ / 4; k4++) {
            float4 wv = w[k4];
            float4 gv = ((const float4*)gp)[k4];
            s += wv.x * gv.x + wv.y * gv.y + wv.z * gv.z + wv.w * gv.w;
        }
        s = fmaxf(s + b_fc1[i], 0.f);
        if (tid < 128) g0[i] = s; else g1[i] = s;
    }
    __syncthreads();
    if (tid < IN_) gd[tid] = g0[tid] - g1[tid];
    __syncthreads();

    #pragma unroll
    for (int dd = 0; dd < 2; dd++) {
        const int d = tid + dd * 256;
        const float4* w = (const float4*)(w_fc2 + d * IN_);
        float s = 0.f;
        #pragma unroll 8
        for (int k4 = 0; k4 < IN_ / 4; k4++) {
            float4 wv = w[k4];
            float4 gv = ((const float4*)gd)[k4];
            s += wv.x * gv.x + wv.y * gv.y + wv.z * gv.z + wv.w * gv.w;
        }
        g_attw[b * DW + d] = 1.f / (1.f + expf(-s));
    }
}

// ---------------------------------------------------------------------------
// GEMM: persistent cg1 tcgen05 (round-13 mainloop) + IN-KERNEL A PREP.
// Warps 11-15 (160 thr) split this CTA's x tiles into pre-swizzled g_x2 slot
// images (2 slots, double-buffered in gmem, L2-hot); warp 10 TMA-loads them.
// Prep is decoupled from the critical path: XF = slot ready, XC = tile fully
// consumed (gates slot overwrite at tt-2). All sync intra-CTA.
// Warp0 MMA, warp1 W producer (3-ring), warps2-9 epilogue.
// ---------------------------------------------------------------------------
#define A_OFF   1024
#define W_OFF   (1024 + 4 * 32768)
#define SMEM_TOTAL (1024 + 4 * 32768 + 3 * 32768)

__global__ __launch_bounds__(512, 1)
void gemm_kernel(const float* __restrict__ x,
                 const float* __restrict__ w_conv,
                 const float* __restrict__ b_conv,
                 float* __restrict__ out)
{
    extern __shared__ __align__(1024) char smem[];
    const int tid = threadIdx.x;

#if USE_TCGEN05
    const uint32_t sb = smem_u32(smem);
    const int wid = tid >> 5, lid = tid & 31;
    const int bid = blockIdx.x;
    const int ntiles = (NTILES_TOTAL - bid + GRID_GEMM - 1) / GRID_GEMM;

    #define WF(s)   (sb + 8   + (s) * 8)
    #define WE(s)   (sb + 32  + (s) * 8)
    #define AF(k)   (sb + 56  + (k) * 8)
    #define AR(k)   (sb + 88  + (k) * 8)
    #define MDN(h)  (sb + 120 + (h) * 8)
    #define EPIF(h) (sb + 136 + (h) * 8)
    const uint32_t XF = sb + 152;   // prep slot ready (count 160)
    const uint32_t XC = sb + 160;   // tile fully consumed (MMA commit)

    if (wid == 0) TCGEN05_ALLOC(sb, 512);
    if (tid == 0) {
        #pragma unroll
        for (int s = 0; s < 3; s++) { MBARRIER_INIT(WF(s), 1); MBARRIER_INIT(WE(s), 1); }
        #pragma unroll
        for (int k = 0; k < 4; k++) { MBARRIER_INIT(AF(k), 1); MBARRIER_INIT(AR(k), 1); }
        MBARRIER_INIT(MDN(0), 1);  MBARRIER_INIT(MDN(1), 1);
        MBARRIER_INIT(EPIF(0), 256); MBARRIER_INIT(EPIF(1), 256);
        MBARRIER_INIT(XF, 160);    MBARRIER_INIT(XC, 1);
    }
    __syncthreads();
    uint32_t tmem;
    asm volatile("ld.shared.b32 %0, [%1];" : "=r"(tmem) : "r"(sb));

    if (wid == 0) {
        // ================= MMA warp =================
        if (elect_one()) {
            int wst = 0;
            int wfph[3] = {0, 0, 0};
            int afph[4] = {0, 0, 0, 0};
            for (int tt = 0; tt < ntiles; tt++) {
                #pragma unroll 1
                for (int h = 0; h < 2; h++) {
                    if (tt > 0) MBARRIER_WAIT_PARITY(EPIF(h), (tt - 1) & 1);
                    const uint32_t dst = tmem + h * 256;
                    #pragma unroll 1
                    for (int kb = 0; kb < 4; kb++) {
                        if (h == 0) { MBARRIER_WAIT_PARITY(AF(kb), afph[kb]); afph[kb] ^= 1; }
                        const uint32_t ab = sb + A_OFF + kb * 32768;
                        const uint64_t ahi = MAKE_SMEM_DESC(ab);
                        const uint64_t alo = MAKE_SMEM_DESC(ab + 16384);
                        // --- whi chunk: (ahi + alo) * whi ---
                        MBARRIER_WAIT_PARITY(WF(wst), wfph[wst]); wfph[wst] ^= 1;
                        {
                            const uint64_t wd = MAKE_SMEM_DESC(sb + W_OFF + wst * 32768);
                            #pragma unroll
                            for (int k = 0; k < 4; k++)
                                mma_f16_ss(dst, ahi + k * 2, wd + k * 2, IDESC, !(kb == 0 && k == 0));
                            #pragma unroll
                            for (int k = 0; k < 4; k++)
                                mma_f16_ss(dst, alo + k * 2, wd + k * 2, IDESC, true);
                            TCGEN05_COMMIT(WE(wst));
                        }
                        wst = (wst == 2) ? 0 : wst + 1;
                        // --- wlo chunk: ahi * wlo ---
                        MBARRIER_WAIT_PARITY(WF(wst), wfph[wst]); wfph[wst] ^= 1;
                        {
                            const uint64_t wd = MAKE_SMEM_DESC(sb + W_OFF + wst * 32768);
                            #pragma unroll
                            for (int k = 0; k < 4; k++)
                                mma_f16_ss(dst, ahi + k * 2, wd + k * 2, IDESC, true);
                            TCGEN05_COMMIT(WE(wst));
                        }
                        wst = (wst == 2) ? 0 : wst + 1;
                        if (h == 1) TCGEN05_COMMIT(AR(kb));   // SMEM A stage free
                    }
                    TCGEN05_COMMIT(MDN(h));                    // half h final
                }
                TCGEN05_COMMIT(XC);                            // tile consumed
            }
        }
    } else if (wid == 1) {
        // ================= W producer: continuous 3-stage ring ==============
        if (elect_one()) {
            const char* wsrc = (const char*)g_w3;
            int wst = 0, wc = 0;
            int weph[3] = {0, 0, 0};
            for (int tt = 0; tt < ntiles; tt++)
                #pragma unroll 1
                for (int h = 0; h < 2; h++)
                    #pragma unroll 1
                    for (int kb = 0; kb < 4; kb++)
                        #pragma unroll
                        for (int isl = 0; isl < 2; isl++) {
                            if (wc >= 3) { MBARRIER_WAIT_PARITY(WE(wst), weph[wst]); weph[wst] ^= 1; }
                            MBARRIER_EXPECT_TX(WF(wst), 32768);
                            BULK_G2S(sb + W_OFF + wst * 32768,
                                     wsrc + (size_t)(kb * 4 + isl * 2 + h) * 32768,
                                     32768, WF(wst));
                            wst = (wst == 2) ? 0 : wst + 1;
                            wc++;
                        }
        }
    } else if (wid <= 9) {
        // ================= Epilogue (8 warps, 256 threads) ==================
        const int cg = (wid <= 5) ? 0 : 1;       // 64-channel sub-group
        const int m  = (wid & 3) * 32 + lid;     // own TMEM subpartition rows
        for (int tt = 0; tt < ntiles; tt++) {
            const int m0 = (bid + GRID_GEMM * tt) * 128;
            const int bb = m0 >> 12;
            const int n  = (m0 & (N_ - 1)) + m;
            float* __restrict__ orow = out + ((size_t)n * B_ + bb) * CH_;
            const float* __restrict__ aw = g_attw + bb * DW;
            #pragma unroll 1
            for (int h = 0; h < 2; h++) {
                MBARRIER_WAIT_PARITY(MDN(h), tt & 1);
                TCGEN05_FENCE_AFTER();
                #pragma unroll
                for (int cc = 0; cc < 2; cc++) {
                    uint32_t hr0[32], hr1[32];
                    TCGEN05_LD_X32(hr0, tmem + h * 256 + cg * 64 + cc * 32);        // radix 0
                    TCGEN05_LD_X32(hr1, tmem + h * 256 + 128 + cg * 64 + cc * 32);  // radix 1
                    TCGEN05_WAIT_LD();
                    #pragma unroll
                    for (int qq = 0; qq < 8; qq++) {
                        const int ch = h * 128 + cg * 64 + cc * 32 + qq * 4;
                        float4 b0 = *(const float4*)&b_conv[ch];
                        float4 b1 = *(const float4*)&b_conv[256 + ch];
                        float4 a0 = *(const float4*)&aw[ch];
                        float4 a1 = *(const float4*)&aw[256 + ch];
                        float4 o;
                        o.x = a0.x * fmaxf(__uint_as_float(hr0[qq*4+0]) + b0.x, 0.f)
                            + a1.x * fmaxf(__uint_as_float(hr1[qq*4+0]) + b1.x, 0.f);
                        o.y = a0.y * fmaxf(__uint_as_float(hr0[qq*4+1]) + b0.y, 0.f)
                            + a1.y * fmaxf(__uint_as_float(hr1[qq*4+1]) + b1.y, 0.f);
                        o.z = a0.z * fmaxf(__uint_as_float(hr0[qq*4+2]) + b0.z, 0.f)
                            + a1.z * fmaxf(__uint_as_float(hr1[qq*4+2]) + b1.z, 0.f);
                        o.w = a0.w * fmaxf(__uint_as_float(hr0[qq*4+3]) + b0.w, 0.f)
                            + a1.w * fmaxf(__uint_as_float(hr1[qq*4+3]) + b1.w, 0.f);
                        *(float4*)(orow + ch) = o;
                    }
                }
                MBARRIER_ARRIVE(EPIF(h));   // TMEM half h free
            }
        }
    } else if (wid == 10) {
        // ================= A producer: cp.async.bulk from own g_x2 slots ====
        if (elect_one()) {
            int arph[4] = {0, 0, 0, 0};
            const char* xbase = (const char*)g_x2 + (size_t)bid * 2 * 131072;
            for (int tt = 0; tt < ntiles; tt++) {
                MBARRIER_WAIT_PARITY(XF, tt & 1);    // slot tt&1 written by prep
                const char* slot = xbase + (size_t)(tt & 1) * 131072;
                #pragma unroll 1
                for (int kb = 0; kb < 4; kb++) {
                    if (tt > 0) { MBARRIER_WAIT_PARITY(AR(kb), arph[kb]); arph[kb] ^= 1; }
                    MBARRIER_EXPECT_TX(AF(kb), 32768);
                    BULK_G2S(sb + A_OFF + kb * 32768, slot + (size_t)kb * 32768, 32768, AF(kb));
                }
            }
        }
    } else {
        // ================= A prep (5 warps, 160 threads) ====================
        const int lt = tid - 352;
        char* xbase = (char*)g_x2 + (size_t)bid * 2 * 131072;
        for (int tt = 0; tt < ntiles; tt++) {
            if (tt >= 2) MBARRIER_WAIT_PARITY(XC, (tt - 2) & 1);   // slot reusable
            const int m0 = (bid + GRID_GEMM * tt) * 128;
            char* slot = xbase + (size_t)(tt & 1) * 131072;
            for (int f = lt; f < 8192; f += 160) {
                const int row = f >> 6;          // 64 float4 per row
                const int c4  = f & 63;
                const int kb  = c4 >> 4;
                const int q4  = c4 & 15;
                const float4 v = *(const float4*)&x[(size_t)(m0 + row) * 256 + c4 * 4];
                uint32_t h01, h23, l01, l23;
                split4(v, h01, h23, l01, l23);
                const uint32_t off = (uint32_t)row * 128 + (((uint32_t)q4 * 8) ^ ((uint32_t)(row & 7) << 4));
                char* img = slot + (size_t)kb * 32768 + off;
                *(uint2*)img           = make_uint2(h01, h23);
                *(uint2*)(img + 16384) = make_uint2(l01, l23);
            }
            __threadfence();                      // STG visible to TMA reads
            MBARRIER_ARRIVE(XF);                  // slot tt&1 ready
        }
    }

    __syncthreads();
    if (wid == 0) { TCGEN05_DEALLOC(tmem, 512); TCGEN05_RELINQ(); }

#else  // ------------------- naive fallback (plain sm_103; dead code) -------
    const int total = B_ * N_;
    for (int row = blockIdx.x; row < total; row += gridDim.x) {
        const int b = row >> 12, n = row & (N_ - 1);
        const float* xr = x + (size_t)row * CIN;
        for (int ch = tid; ch < CH_; ch += blockDim.x) {
            float s0 = 0.f, s1 = 0.f;
            for (int k = 0; k < CIN; k++) {
                const float xv = xr[k];
                s0 += xv * w_conv[(size_t)ch * CIN + k];
                s1 += xv * w_conv[(size_t)(256 + ch) * CIN + k];
            }
            const float h0v = fmaxf(s0 + b_conv[ch], 0.f);
            const float h1v = fmaxf(s1 + b_conv[256 + ch], 0.f);
            out[((size_t)n * B_ + b) * CH_ + ch] =
                g_attw[b * DW + ch] * h0v + g_attw[b * DW + 256 + ch] * h1v;
        }
    }
#endif
}

extern "C" void kernel_launch(void* const* d_in, const int* in_sizes, int n_in,
                              void* d_out, int out_size) {
    const float* x      = (const float*)d_in[0];
    const float* w_conv = (const float*)d_in[1];
    const float* b_conv = (const float*)d_in[2];
    const float* w_fc1  = (const float*)d_in[3];
    const float* b_fc1  = (const float*)d_in[4];
    const float* w_fc2  = (const float*)d_in[5];
    // d_in[6] = b_fc2: cancels in the softmax-pair difference, unused.
    float* out = (float*)d_out;

    cudaFuncSetAttribute(gemm_kernel, cudaFuncAttributeMaxDynamicSharedMemorySize, SMEM_TOTAL);

    setup_kernel<<<144, 256>>>(x, w_conv, b_conv, w_fc1, b_fc1, w_fc2);
    gemm_kernel<<<GRID_GEMM, 512, SMEM_TOTAL>>>(x, w_conv, b_conv, out);
}

// round 15
// speedup vs baseline: 1.0350x; 1.0350x over previous
#include <cuda_runtime.h>
#include <cuda_bf16.h>
#include <cstdint>
#include <math.h>

#define B_    16
#define N_    4096
#define CIN   256
#define CH_   256
#define DW    512
#define IN_   128
#define GRID_GEMM 128

// tcgen05 asm only compiles under an 'a'-suffixed target pass.
#if defined(__CUDA_ARCH_FEAT_SM103_ALL) || defined(__CUDA_ARCH_FEAT_SM100_ALL) || defined(__CUDA_ARCH_FEAT_SM101_ALL)
#define USE_TCGEN05 1
#else
#define USE_TCGEN05 0
#endif

// -------------------- device scratch --------------------
__device__ float g_attw[B_ * DW];
// W: 16 pre-swizzled 32KB images (256 rows x 128B, SW128 baked in).
// image j = kb*4 + islo*2 + h.  Row perm: w_conv row d (c=d&255, r=d>>8) ->
// h=c>>7, lrow=(c&127)+r*128.  D col (N=256 MMA for channel-half h) = lrow.
__device__ __nv_bfloat16 g_w3[16 * 256 * 64];
// A: pre-split, pre-swizzled SMEM-ready images: [tile128][kb][hi 16KB|lo 16KB].
__device__ __nv_bfloat16 g_x2[(size_t)512 * 4 * 16384];

// -------------------- PTX helpers --------------------
__device__ __forceinline__ uint32_t smem_u32(const void* p) {
    uint32_t a;
    asm("{ .reg .u64 t; cvta.to.shared.u64 t, %1; cvt.u32.u64 %0, t; }" : "=r"(a) : "l"(p));
    return a;
}
__device__ __forceinline__ uint32_t elect_one() {
    uint32_t pred;
    asm volatile("{\n\t.reg .pred p;\n\telect.sync _|p, 0xFFFFFFFF;\n\tselp.b32 %0, 1, 0, p;\n\t}" : "=r"(pred));
    return pred;
}
#define TCGEN05_ALLOC(sa, n) \
    asm volatile("tcgen05.alloc.cta_group::1.sync.aligned.shared::cta.b32 [%0], %1;" :: "r"((uint32_t)(sa)), "r"((uint32_t)(n)) : "memory")
#define TCGEN05_DEALLOC(t, n) \
    asm volatile("tcgen05.dealloc.cta_group::1.sync.aligned.b32 %0, %1;" :: "r"(t), "r"((uint32_t)(n)))
#define TCGEN05_RELINQ() \
    asm volatile("tcgen05.relinquish_alloc_permit.cta_group::1.sync.aligned;")
#define TCGEN05_COMMIT(mb) \
    asm volatile("tcgen05.commit.cta_group::1.mbarrier::arrive::one.shared::cluster.b64 [%0];" :: "r"((uint32_t)(mb)) : "memory")
#define TCGEN05_WAIT_LD() asm volatile("tcgen05.wait::ld.sync.aligned;" ::: "memory")
#define TCGEN05_FENCE_AFTER() asm volatile("tcgen05.fence::after_thread_sync;" ::: "memory")
#define MBARRIER_INIT(mb, cnt) \
    asm volatile("mbarrier.init.shared.b64 [%0], %1;" :: "r"((uint32_t)(mb)), "r"((uint32_t)(cnt)) : "memory")
#define MBARRIER_ARRIVE(mb) \
    asm volatile("mbarrier.arrive.shared.b64 _, [%0];" :: "r"((uint32_t)(mb)) : "memory")
#define MBARRIER_EXPECT_TX(mb, bytes) \
    asm volatile("mbarrier.arrive.expect_tx.shared.b64 _, [%0], %1;" :: "r"((uint32_t)(mb)), "r"((uint32_t)(bytes)) : "memory")
#define MBARRIER_WAIT_PARITY(mb, ph) do { \
    uint32_t _m = (uint32_t)(mb), _p = (uint32_t)(ph), _d; \
    asm volatile("{\n\t.reg .pred p;\n\tmbarrier.try_wait.parity.acquire.cta.shared::cta.b64 p, [%1], %2;\n\tselp.b32 %0, 1, 0, p;\n\t}" \
        : "=r"(_d) : "r"(_m), "r"(_p) : "memory"); \
    if (!_d) { \
        asm volatile("{\n\t.reg .pred P1;\n\tWL_%=:\n\tmbarrier.try_wait.parity.acquire.cta.shared::cta.b64 P1, [%0], %1, 0x989680;\n\t@P1 bra.uni WD_%=;\n\tbra.uni WL_%=;\n\tWD_%=:\n\t}" \
            :: "r"(_m), "r"(_p) : "memory"); \
    } \
} while (0)
#define BULK_G2S(dst, src, bytes, mb) \
    asm volatile("cp.async.bulk.shared::cta.global.mbarrier::complete_tx::bytes [%0], [%1], %2, [%3];" \
        :: "r"((uint32_t)(dst)), "l"(src), "r"((uint32_t)(bytes)), "r"((uint32_t)(mb)) : "memory")
#define TCGEN05_LD_X32(r, ta) \
    asm volatile("tcgen05.ld.sync.aligned.32x32b.x32.b32 " \
        "{%0,%1,%2,%3,%4,%5,%6,%7,%8,%9,%10,%11,%12,%13,%14,%15," \
        "%16,%17,%18,%19,%20,%21,%22,%23,%24,%25,%26,%27,%28,%29,%30,%31}, [%32];" \
        : "=r"((r)[0]),"=r"((r)[1]),"=r"((r)[2]),"=r"((r)[3]),"=r"((r)[4]),"=r"((r)[5]),"=r"((r)[6]),"=r"((r)[7]), \
          "=r"((r)[8]),"=r"((r)[9]),"=r"((r)[10]),"=r"((r)[11]),"=r"((r)[12]),"=r"((r)[13]),"=r"((r)[14]),"=r"((r)[15]), \
          "=r"((r)[16]),"=r"((r)[17]),"=r"((r)[18]),"=r"((r)[19]),"=r"((r)[20]),"=r"((r)[21]),"=r"((r)[22]),"=r"((r)[23]), \
          "=r"((r)[24]),"=r"((r)[25]),"=r"((r)[26]),"=r"((r)[27]),"=r"((r)[28]),"=r"((r)[29]),"=r"((r)[30]),"=r"((r)[31]) \
        : "r"(ta))

static constexpr uint64_t SMEM_DESC_BASE_SW128 =
    (uint64_t(2) << 61) | (uint64_t(1) << 46) | (uint64_t(64) << 32) | (uint64_t(1) << 16);
#define MAKE_SMEM_DESC(a) (SMEM_DESC_BASE_SW128 | ((uint64_t)((a) >> 4) & 0x3FFF))

#if USE_TCGEN05
// SS-mode cg1 bf16 MMA: D[128,256] += A[128,16] * B[256,16]^T
__device__ __forceinline__ void mma_f16_ss(uint32_t d, uint64_t ad, uint64_t bd, uint32_t idesc, bool acc) {
    uint32_t en = acc ? 1u : 0u;
    asm volatile(
        "{\n\t.reg .pred p;\n\tsetp.ne.u32 p, %5, 0;\n\t"
        "tcgen05.mma.cta_group::1.kind::f16 [%0], %1, %2, %3, {%4, %4, %4, %4}, p;\n\t}"
        :: "r"(d), "l"(ad), "l"(bd), "r"(idesc), "r"(0u), "r"(en) : "memory");
}
#endif
// idesc: F32 accum, BF16 x BF16, M=128, N=256
static constexpr uint32_t IDESC =
    (1u << 4) | (1u << 7) | (1u << 10) | ((256u / 8u) << 17) | ((128u / 16u) << 24);

// fp32 -> bf16 hi/lo split, packed pairs
__device__ __forceinline__ void split4(const float4 v, uint32_t& h01, uint32_t& h23,
                                       uint32_t& l01, uint32_t& l23) {
    __nv_bfloat162 h0 = __floats2bfloat162_rn(v.x, v.y);
    __nv_bfloat162 h1 = __floats2bfloat162_rn(v.z, v.w);
    __nv_bfloat162 l0 = __floats2bfloat162_rn(v.x - __bfloat162float(h0.x),
                                              v.y - __bfloat162float(h0.y));
    __nv_bfloat162 l1 = __floats2bfloat162_rn(v.z - __bfloat162float(h1.x),
                                              v.w - __bfloat162float(h1.y));
    h01 = *(uint32_t*)&h0; h23 = *(uint32_t*)&h1;
    l01 = *(uint32_t*)&l0; l23 = *(uint32_t*)&l1;
}

// ---------------------------------------------------------------------------
// Setup (single launch, 4176 blocks x 512):
//   blocks 0..15    attention chain (conv inline; rSoftMax slice -> sigmoid)
//   blocks 16..79   prep_w
//   blocks 80..4175 prep_x (8 floats/thread, uint4 hi + uint4 lo stores)
// ---------------------------------------------------------------------------
__global__ __launch_bounds__(512) void setup_kernel(
    const float* __restrict__ x,
    const float* __restrict__ w_conv,
    const float* __restrict__ b_conv,
    const float* __restrict__ w_fc1,
    const float* __restrict__ b_fc1,
    const float* __restrict__ w_fc2)
{
    const int tid = threadIdx.x;

    if (blockIdx.x >= 80) {
        // ---- prep_x ----
        const size_t fi = ((size_t)(blockIdx.x - 80) * 512 + tid) * 8;
        float4 v0 = *(const float4*)(x + fi);
        float4 v1 = *(const float4*)(x + fi + 4);
        uint32_t h01, h23, l01, l23, h45, h67, l45, l67;
        split4(v0, h01, h23, l01, l23);
        split4(v1, h45, h67, l45, l67);
        const int row  = (int)(fi >> 8);
        const int k    = (int)(fi & 255);
        const int tile = row >> 7, lrow = row & 127;
        const int kb   = k >> 6,  q8   = (k & 63) >> 3;
        const uint32_t off = (uint32_t)lrow * 128 + (((uint32_t)q8 * 16) ^ ((uint32_t)(lrow & 7) << 4));
        char* img = (char*)g_x2 + ((size_t)(tile * 4 + kb)) * 32768 + off;
        *(uint4*)img           = make_uint4(h01, h23, h45, h67);
        *(uint4*)(img + 16384) = make_uint4(l01, l23, l45, l67);
        return;
    }

    if (blockIdx.x >= 16) {
        // ---- prep_w ----
        const int gi = ((blockIdx.x - 16) * 512 + tid) * 4;
        float4 v = *(const float4*)(w_conv + gi);
        const int d = gi >> 8, k = gi & 255;
        uint32_t h01, h23, l01, l23;
        split4(v, h01, h23, l01, l23);
        const int c = d & 255, r = d >> 8;
        const int nh = c >> 7;
        const int lrow = (c & 127) + (r << 7);
        const int kb = k >> 6, kc = k & 63;
        const uint32_t off = (uint32_t)lrow * 128 + (((uint32_t)kc * 2) ^ ((uint32_t)(lrow & 7) << 4));
        char* basehi = (char*)g_w3 + (size_t)(kb * 4 + nh) * 32768 + off;
        char* baselo = (char*)g_w3 + (size_t)(kb * 4 + 2 + nh) * 32768 + off;
        *(uint2*)basehi = make_uint2(h01, h23);
        *(uint2*)baselo = make_uint2(l01, l23);
        return;
    }

    // ---- attention (conv inline, 512 threads: one conv output per thread) ----
    const int b = blockIdx.x;
    __shared__ float xs0[CIN], xs1[CIN];
    __shared__ float h0[DW], h1[DW];
    __shared__ float gap0[CH_], gap1[CH_];
    __shared__ float g0[IN_], g1[IN_], gd[IN_];

    if (tid < CIN) {
        xs0[tid] = x[(b * N_ + 0)    * CIN + tid];
        xs1[tid] = x[(b * N_ + 1024) * CIN + tid];
    }
    __syncthreads();

    {
        const int d = tid;
        const float4* w = (const float4*)(w_conv + d * CIN);
        float s0 = 0.f, s1 = 0.f;
        #pragma unroll 8
        for (int k4 = 0; k4 < CIN / 4; k4++) {
            float4 wv = w[k4];
            float4 x0 = ((const float4*)xs0)[k4];
            float4 x1 = ((const float4*)xs1)[k4];
            s0 += wv.x * x0.x + wv.y * x0.y + wv.z * x0.z + wv.w * x0.w;
            s1 += wv.x * x1.x + wv.y * x1.y + wv.z * x1.z + wv.w * x1.w;
        }
        const float bb = b_conv[d];
        h0[d] = fmaxf(s0 + bb, 0.f);
        h1[d] = fmaxf(s1 + bb, 0.f);
    }
    __syncthreads();

    if (tid < CH_) {
        gap0[tid] = h0[tid] + h0[tid + CH_];
        gap1[tid] = h1[tid] + h1[tid + CH_];
    }
    __syncthreads();

    if (tid < 256) {
        const int i = tid & 127;
        const float* gp = (tid < 128) ? gap0 : gap1;
        const float4* w = (const float4*)(w_fc1 + i * CH_);
        float s = 0.f;
        #pragma unroll 8
        for (int k4 = 0; k4 < CH_ / 4; k4++) {
            float4 wv = w[k4];
            float4 gv = ((const float4*)gp)[k4];
            s += wv.x * gv.x + wv.y * gv.y + wv.z * gv.z + wv.w * gv.w;
        }
        s = fmaxf(s + b_fc1[i], 0.f);
        if (tid < 128) g0[i] = s; else g1[i] = s;
    }
    __syncthreads();
    if (tid < IN_) gd[tid] = g0[tid] - g1[tid];
    __syncthreads();

    {
        const int d = tid;
        const float4* w = (const float4*)(w_fc2 + d * IN_);
        float s = 0.f;
        #pragma unroll 8
        for (int k4 = 0; k4 < IN_ / 4; k4++) {
            float4 wv = w[k4];
            float4 gv = ((const float4*)gd)[k4];
            s += wv.x * gv.x + wv.y * gv.y + wv.z * gv.z + wv.w * gv.w;
        }
        g_attw[b * DW + d] = 1.f / (1.f + expf(-s));
    }
}

// ---------------------------------------------------------------------------
// GEMM: persistent cg1 tcgen05, M=256 SUPER-TILES with async A.
// Two 128-row m-subs share every W chunk (W rate ~16B/cyc/SM, well under LTS
// cap). TMEM: m-sub s -> cols s*256..s*256+255 for the CURRENT channel-half
// phase; 4 phases gp = u*2+h are strictly serialized on TMEM (round-10
// discipline: MMA waits EPIF of gp-1; epilogue waits MDN of gp).
// A: 2-stage 64KB ring fed by cp.async.bulk from g_x2 (reread per h, L2-hot).
// W: 3-stage 32KB ring. Warp0 MMA, warp1 W-prod, warps2-9 epilogue, w10 A-prod.
// Grid 128 x 2 super-tiles, perfectly balanced.
// ---------------------------------------------------------------------------
#define A_OFF   1024
#define W_OFF   (1024 + 2 * 65536)
#define SMEM_TOTAL (1024 + 2 * 65536 + 3 * 32768)

__global__ __launch_bounds__(352, 1)
void gemm_kernel(const float* __restrict__ x,
                 const float* __restrict__ w_conv,
                 const float* __restrict__ b_conv,
                 float* __restrict__ out)
{
    extern __shared__ __align__(1024) char smem[];
    const int tid = threadIdx.x;

#if USE_TCGEN05
    const uint32_t sb = smem_u32(smem);
    const int wid = tid >> 5, lid = tid & 31;
    const int bid = blockIdx.x;

    #define WF(s)  (sb + 8  + (s) * 8)
    #define WE(s)  (sb + 32 + (s) * 8)
    #define AF(q)  (sb + 56 + (q) * 8)
    #define AR(q)  (sb + 72 + (q) * 8)
    const uint32_t MDN  = sb + 88;
    const uint32_t EPIF = sb + 96;

    if (wid == 0) TCGEN05_ALLOC(sb, 512);
    if (tid == 0) {
        #pragma unroll
        for (int s = 0; s < 3; s++) { MBARRIER_INIT(WF(s), 1); MBARRIER_INIT(WE(s), 1); }
        MBARRIER_INIT(AF(0), 1); MBARRIER_INIT(AF(1), 1);
        MBARRIER_INIT(AR(0), 1); MBARRIER_INIT(AR(1), 1);
        MBARRIER_INIT(MDN, 1);   MBARRIER_INIT(EPIF, 256);
    }
    __syncthreads();
    uint32_t tmem;
    asm volatile("ld.shared.b32 %0, [%1];" : "=r"(tmem) : "r"(sb));

    if (wid == 0) {
        // ================= MMA warp =================
        if (elect_one()) {
            int wst = 0, chunk = 0;
            int wfph[3] = {0, 0, 0};
            int afph[2] = {0, 0};
            for (int gp = 0; gp < 4; gp++) {
                if (gp > 0) MBARRIER_WAIT_PARITY(EPIF, (gp - 1) & 1);
                #pragma unroll 1
                for (int kb = 0; kb < 4; kb++) {
                    const int q = chunk & 1;
                    MBARRIER_WAIT_PARITY(AF(q), afph[q]); afph[q] ^= 1;
                    const uint32_t abase = sb + A_OFF + q * 65536;
                    // --- whi chunk: (ahi + alo) * whi, both m-subs ---
                    MBARRIER_WAIT_PARITY(WF(wst), wfph[wst]); wfph[wst] ^= 1;
                    {
                        const uint64_t wd = MAKE_SMEM_DESC(sb + W_OFF + wst * 32768);
                        #pragma unroll
                        for (int s = 0; s < 2; s++) {
                            const uint32_t dst = tmem + s * 256;
                            const uint64_t ah = MAKE_SMEM_DESC(abase + s * 32768);
                            const uint64_t al = MAKE_SMEM_DESC(abase + s * 32768 + 16384);
                            #pragma unroll
                            for (int k = 0; k < 4; k++)
                                mma_f16_ss(dst, ah + k * 2, wd + k * 2, IDESC, !(kb == 0 && k == 0));
                            #pragma unroll
                            for (int k = 0; k < 4; k++)
                                mma_f16_ss(dst, al + k * 2, wd + k * 2, IDESC, true);
                        }
                        TCGEN05_COMMIT(WE(wst));
                    }
                    wst = (wst == 2) ? 0 : wst + 1;
                    // --- wlo chunk: ahi * wlo, both m-subs ---
                    MBARRIER_WAIT_PARITY(WF(wst), wfph[wst]); wfph[wst] ^= 1;
                    {
                        const uint64_t wd = MAKE_SMEM_DESC(sb + W_OFF + wst * 32768);
                        #pragma unroll
                        for (int s = 0; s < 2; s++) {
                            const uint32_t dst = tmem + s * 256;
                            const uint64_t ah = MAKE_SMEM_DESC(abase + s * 32768);
                            #pragma unroll
                            for (int k = 0; k < 4; k++)
                                mma_f16_ss(dst, ah + k * 2, wd + k * 2, IDESC, true);
                        }
                        TCGEN05_COMMIT(WE(wst));
                    }
                    wst = (wst == 2) ? 0 : wst + 1;
                    TCGEN05_COMMIT(AR(q));
                    chunk++;
                }
                TCGEN05_COMMIT(MDN);   // phase gp accumulators final
            }
        }
    } else if (wid == 1) {
        // ================= W producer: continuous 3-stage ring ==============
        if (elect_one()) {
            const char* wsrc = (const char*)g_w3;
            int wst = 0, wc = 0;
            int weph[3] = {0, 0, 0};
            for (int gp = 0; gp < 4; gp++) {
                const int h = gp & 1;
                #pragma unroll 1
                for (int kb = 0; kb < 4; kb++)
                    #pragma unroll
                    for (int isl = 0; isl < 2; isl++) {
                        if (wc >= 3) { MBARRIER_WAIT_PARITY(WE(wst), weph[wst]); weph[wst] ^= 1; }
                        MBARRIER_EXPECT_TX(WF(wst), 32768);
                        BULK_G2S(sb + W_OFF + wst * 32768,
                                 wsrc + (size_t)(kb * 4 + isl * 2 + h) * 32768,
                                 32768, WF(wst));
                        wst = (wst == 2) ? 0 : wst + 1;
                        wc++;
                    }
            }
        }
    } else if (wid <= 9) {
        // ================= Epilogue (8 warps): 2-5 m-sub0, 6-9 m-sub1 =======
        const int sub = (wid <= 5) ? 0 : 1;
        const int m   = (wid & 3) * 32 + lid;       // own TMEM subpartition rows
        for (int gp = 0; gp < 4; gp++) {
            const int u = gp >> 1, h = gp & 1;
            const int stile = bid + GRID_GEMM * u;
            const int m0 = stile * 256;
            const int bb = m0 >> 12;
            const int n  = (m0 & (N_ - 1)) + sub * 128 + m;
            float* __restrict__ orow = out + ((size_t)n * B_ + bb) * CH_;
            const float* __restrict__ aw = g_attw + bb * DW;
            MBARRIER_WAIT_PARITY(MDN, gp & 1);
            TCGEN05_FENCE_AFTER();
            #pragma unroll 1
            for (int cc = 0; cc < 4; cc++) {
                uint32_t hr0[32], hr1[32];
                TCGEN05_LD_X32(hr0, tmem + sub * 256 + cc * 32);         // radix 0
                TCGEN05_LD_X32(hr1, tmem + sub * 256 + 128 + cc * 32);   // radix 1
                TCGEN05_WAIT_LD();
                #pragma unroll
                for (int qq = 0; qq < 8; qq++) {
                    const int ch = h * 128 + cc * 32 + qq * 4;
                    float4 b0 = *(const float4*)&b_conv[ch];
                    float4 b1 = *(const float4*)&b_conv[256 + ch];
                    float4 a0 = *(const float4*)&aw[ch];
                    float4 a1 = *(const float4*)&aw[256 + ch];
                    float4 o;
                    o.x = a0.x * fmaxf(__uint_as_float(hr0[qq*4+0]) + b0.x, 0.f)
                        + a1.x * fmaxf(__uint_as_float(hr1[qq*4+0]) + b1.x, 0.f);
                    o.y = a0.y * fmaxf(__uint_as_float(hr0[qq*4+1]) + b0.y, 0.f)
                        + a1.y * fmaxf(__uint_as_float(hr1[qq*4+1]) + b1.y, 0.f);
                    o.z = a0.z * fmaxf(__uint_as_float(hr0[qq*4+2]) + b0.z, 0.f)
                        + a1.z * fmaxf(__uint_as_float(hr1[qq*4+2]) + b1.z, 0.f);
                    o.w = a0.w * fmaxf(__uint_as_float(hr0[qq*4+3]) + b0.w, 0.f)
                        + a1.w * fmaxf(__uint_as_float(hr1[qq*4+3]) + b1.w, 0.f);
                    *(float4*)(orow + ch) = o;
                }
            }
            MBARRIER_ARRIVE(EPIF);   // TMEM free for next phase
        }
    } else if (wid == 10) {
        // ================= A producer: cp.async.bulk from g_x2 =============
        if (elect_one()) {
            int arph[2] = {0, 0};
            int chunk = 0;
            for (int gp = 0; gp < 4; gp++) {
                const int u = gp >> 1;
                const int stile = bid + GRID_GEMM * u;
                #pragma unroll 1
                for (int kb = 0; kb < 4; kb++) {
                    const int q = chunk & 1;
                    if (chunk >= 2) { MBARRIER_WAIT_PARITY(AR(q), arph[q]); arph[q] ^= 1; }
                    MBARRIER_EXPECT_TX(AF(q), 65536);
                    #pragma unroll
                    for (int s = 0; s < 2; s++)
                        BULK_G2S(sb + A_OFF + q * 65536 + s * 32768,
                                 (const char*)g_x2 + (size_t)((stile * 2 + s) * 4 + kb) * 32768,
                                 32768, AF(q));
                    chunk++;
                }
            }
        }
    }

    __syncthreads();
    if (wid == 0) { TCGEN05_DEALLOC(tmem, 512); TCGEN05_RELINQ(); }

#else  // ------------------- naive fallback (plain sm_103; dead code) -------
    const int total = B_ * N_;
    for (int row = blockIdx.x; row < total; row += gridDim.x) {
        const int b = row >> 12, n = row & (N_ - 1);
        const float* xr = x + (size_t)row * CIN;
        for (int ch = tid; ch < CH_; ch += blockDim.x) {
            float s0 = 0.f, s1 = 0.f;
            for (int k = 0; k < CIN; k++) {
                const float xv = xr[k];
                s0 += xv * w_conv[(size_t)ch * CIN + k];
                s1 += xv * w_conv[(size_t)(256 + ch) * CIN + k];
            }
            const float h0v = fmaxf(s0 + b_conv[ch], 0.f);
            const float h1v = fmaxf(s1 + b_conv[256 + ch], 0.f);
            out[((size_t)n * B_ + b) * CH_ + ch] =
                g_attw[b * DW + ch] * h0v + g_attw[b * DW + 256 + ch] * h1v;
        }
    }
#endif
}

extern "C" void kernel_launch(void* const* d_in, const int* in_sizes, int n_in,
                              void* d_out, int out_size) {
    const float* x      = (const float*)d_in[0];
    const float* w_conv = (const float*)d_in[1];
    const float* b_conv = (const float*)d_in[2];
    const float* w_fc1  = (const float*)d_in[3];
    const float* b_fc1  = (const float*)d_in[4];
    const float* w_fc2  = (const float*)d_in[5];
    // d_in[6] = b_fc2: cancels in the softmax-pair difference, unused.
    float* out = (float*)d_out;

    cudaFuncSetAttribute(gemm_kernel, cudaFuncAttributeMaxDynamicSharedMemorySize, SMEM_TOTAL);

    setup_kernel<<<16 + 64 + 4096, 512>>>(x, w_conv, b_conv, w_fc1, b_fc1, w_fc2);
    gemm_kernel<<<GRID_GEMM, 352, SMEM_TOTAL>>>(x, w_conv, b_conv, out);
}

// round 16
// speedup vs baseline: 1.1112x; 1.0736x over previous
#include <cuda_runtime.h>
#include <cuda_bf16.h>
#include <cstdint>
#include <math.h>

#define B_    16
#define N_    4096
#define CIN   256
#define CH_   256
#define DW    512
#define IN_   128
#define NTILES_TOTAL 512
#define GRID_GEMM 148

// tcgen05 asm only compiles under an 'a'-suffixed target pass.
#if defined(__CUDA_ARCH_FEAT_SM103_ALL) || defined(__CUDA_ARCH_FEAT_SM100_ALL) || defined(__CUDA_ARCH_FEAT_SM101_ALL)
#define USE_TCGEN05 1
#else
#define USE_TCGEN05 0
#endif

// -------------------- device scratch --------------------
__device__ float g_attw[B_ * DW];
// W: 16 pre-swizzled 32KB images (256 rows x 128B, SW128 baked in).
// image j = kb*4 + islo*2 + h.  Row perm: w_conv row d (c=d&255, r=d>>8) ->
// h=c>>7, lrow=(c&127)+r*128.  D col (N=256 MMA for channel-half h) = lrow.
__device__ __nv_bfloat16 g_w3[16 * 256 * 64];
// A: pre-split, pre-swizzled SMEM-ready images: [tile128][kb][hi 16KB|lo 16KB].
__device__ __nv_bfloat16 g_x2[(size_t)NTILES_TOTAL * 4 * 16384];

// -------------------- PTX helpers --------------------
__device__ __forceinline__ uint32_t smem_u32(const void* p) {
    uint32_t a;
    asm("{ .reg .u64 t; cvta.to.shared.u64 t, %1; cvt.u32.u64 %0, t; }" : "=r"(a) : "l"(p));
    return a;
}
__device__ __forceinline__ uint32_t elect_one() {
    uint32_t pred;
    asm volatile("{\n\t.reg .pred p;\n\telect.sync _|p, 0xFFFFFFFF;\n\tselp.b32 %0, 1, 0, p;\n\t}" : "=r"(pred));
    return pred;
}
#define TCGEN05_ALLOC(sa, n) \
    asm volatile("tcgen05.alloc.cta_group::1.sync.aligned.shared::cta.b32 [%0], %1;" :: "r"((uint32_t)(sa)), "r"((uint32_t)(n)) : "memory")
#define TCGEN05_DEALLOC(t, n) \
    asm volatile("tcgen05.dealloc.cta_group::1.sync.aligned.b32 %0, %1;" :: "r"(t), "r"((uint32_t)(n)))
#define TCGEN05_RELINQ() \
    asm volatile("tcgen05.relinquish_alloc_permit.cta_group::1.sync.aligned;")
#define TCGEN05_COMMIT(mb) \
    asm volatile("tcgen05.commit.cta_group::1.mbarrier::arrive::one.shared::cluster.b64 [%0];" :: "r"((uint32_t)(mb)) : "memory")
#define TCGEN05_WAIT_LD() asm volatile("tcgen05.wait::ld.sync.aligned;" ::: "memory")
#define TCGEN05_FENCE_AFTER() asm volatile("tcgen05.fence::after_thread_sync;" ::: "memory")
#define MBARRIER_INIT(mb, cnt) \
    asm volatile("mbarrier.init.shared.b64 [%0], %1;" :: "r"((uint32_t)(mb)), "r"((uint32_t)(cnt)) : "memory")
#define MBARRIER_ARRIVE(mb) \
    asm volatile("mbarrier.arrive.shared.b64 _, [%0];" :: "r"((uint32_t)(mb)) : "memory")
#define MBARRIER_EXPECT_TX(mb, bytes) \
    asm volatile("mbarrier.arrive.expect_tx.shared.b64 _, [%0], %1;" :: "r"((uint32_t)(mb)), "r"((uint32_t)(bytes)) : "memory")
#define MBARRIER_WAIT_PARITY(mb, ph) do { \
    uint32_t _m = (uint32_t)(mb), _p = (uint32_t)(ph), _d; \
    asm volatile("{\n\t.reg .pred p;\n\tmbarrier.try_wait.parity.acquire.cta.shared::cta.b64 p, [%1], %2;\n\tselp.b32 %0, 1, 0, p;\n\t}" \
        : "=r"(_d) : "r"(_m), "r"(_p) : "memory"); \
    if (!_d) { \
        asm volatile("{\n\t.reg .pred P1;\n\tWL_%=:\n\tmbarrier.try_wait.parity.acquire.cta.shared::cta.b64 P1, [%0], %1, 0x989680;\n\t@P1 bra.uni WD_%=;\n\tbra.uni WL_%=;\n\tWD_%=:\n\t}" \
            :: "r"(_m), "r"(_p) : "memory"); \
    } \
} while (0)
#define BULK_G2S(dst, src, bytes, mb) \
    asm volatile("cp.async.bulk.shared::cta.global.mbarrier::complete_tx::bytes [%0], [%1], %2, [%3];" \
        :: "r"((uint32_t)(dst)), "l"(src), "r"((uint32_t)(bytes)), "r"((uint32_t)(mb)) : "memory")
#define TCGEN05_LD_X32(r, ta) \
    asm volatile("tcgen05.ld.sync.aligned.32x32b.x32.b32 " \
        "{%0,%1,%2,%3,%4,%5,%6,%7,%8,%9,%10,%11,%12,%13,%14,%15," \
        "%16,%17,%18,%19,%20,%21,%22,%23,%24,%25,%26,%27,%28,%29,%30,%31}, [%32];" \
        : "=r"((r)[0]),"=r"((r)[1]),"=r"((r)[2]),"=r"((r)[3]),"=r"((r)[4]),"=r"((r)[5]),"=r"((r)[6]),"=r"((r)[7]), \
          "=r"((r)[8]),"=r"((r)[9]),"=r"((r)[10]),"=r"((r)[11]),"=r"((r)[12]),"=r"((r)[13]),"=r"((r)[14]),"=r"((r)[15]), \
          "=r"((r)[16]),"=r"((r)[17]),"=r"((r)[18]),"=r"((r)[19]),"=r"((r)[20]),"=r"((r)[21]),"=r"((r)[22]),"=r"((r)[23]), \
          "=r"((r)[24]),"=r"((r)[25]),"=r"((r)[26]),"=r"((r)[27]),"=r"((r)[28]),"=r"((r)[29]),"=r"((r)[30]),"=r"((r)[31]) \
        : "r"(ta))

static constexpr uint64_t SMEM_DESC_BASE_SW128 =
    (uint64_t(2) << 61) | (uint64_t(1) << 46) | (uint64_t(64) << 32) | (uint64_t(1) << 16);
#define MAKE_SMEM_DESC(a) (SMEM_DESC_BASE_SW128 | ((uint64_t)((a) >> 4) & 0x3FFF))

#if USE_TCGEN05
// SS-mode cg1 bf16 MMA: D[128,256] += A[128,16] * B[256,16]^T
__device__ __forceinline__ void mma_f16_ss(uint32_t d, uint64_t ad, uint64_t bd, uint32_t idesc, bool acc) {
    uint32_t en = acc ? 1u : 0u;
    asm volatile(
        "{\n\t.reg .pred p;\n\tsetp.ne.u32 p, %5, 0;\n\t"
        "tcgen05.mma.cta_group::1.kind::f16 [%0], %1, %2, %3, {%4, %4, %4, %4}, p;\n\t}"
        :: "r"(d), "l"(ad), "l"(bd), "r"(idesc), "r"(0u), "r"(en) : "memory");
}
#endif
// idesc: F32 accum, BF16 x BF16, M=128, N=256
static constexpr uint32_t IDESC =
    (1u << 4) | (1u << 7) | (1u << 10) | ((256u / 8u) << 17) | ((128u / 16u) << 24);

// fp32 -> bf16 hi/lo split, packed pairs
__device__ __forceinline__ void split4(const float4 v, uint32_t& h01, uint32_t& h23,
                                       uint32_t& l01, uint32_t& l23) {
    __nv_bfloat162 h0 = __floats2bfloat162_rn(v.x, v.y);
    __nv_bfloat162 h1 = __floats2bfloat162_rn(v.z, v.w);
    __nv_bfloat162 l0 = __floats2bfloat162_rn(v.x - __bfloat162float(h0.x),
                                              v.y - __bfloat162float(h0.y));
    __nv_bfloat162 l1 = __floats2bfloat162_rn(v.z - __bfloat162float(h1.x),
                                              v.w - __bfloat162float(h1.y));
    h01 = *(uint32_t*)&h0; h23 = *(uint32_t*)&h1;
    l01 = *(uint32_t*)&l0; l23 = *(uint32_t*)&l1;
}

// ---------------------------------------------------------------------------
// Setup (single launch, 4176 blocks x 512) — unchanged from round 15:
//   blocks 0..15    attention chain; 16..79 prep_w; 80..4175 prep_x.
// ---------------------------------------------------------------------------
__global__ __launch_bounds__(512) void setup_kernel(
    const float* __restrict__ x,
    const float* __restrict__ w_conv,
    const float* __restrict__ b_conv,
    const float* __restrict__ w_fc1,
    const float* __restrict__ b_fc1,
    const float* __restrict__ w_fc2)
{
    const int tid = threadIdx.x;

    if (blockIdx.x >= 80) {
        // ---- prep_x: 8 floats/thread, uint4 hi + uint4 lo ----
        const size_t fi = ((size_t)(blockIdx.x - 80) * 512 + tid) * 8;
        float4 v0 = *(const float4*)(x + fi);
        float4 v1 = *(const float4*)(x + fi + 4);
        uint32_t h01, h23, l01, l23, h45, h67, l45, l67;
        split4(v0, h01, h23, l01, l23);
        split4(v1, h45, h67, l45, l67);
        const int row  = (int)(fi >> 8);
        const int k    = (int)(fi & 255);
        const int tile = row >> 7, lrow = row & 127;
        const int kb   = k >> 6,  q8   = (k & 63) >> 3;
        const uint32_t off = (uint32_t)lrow * 128 + (((uint32_t)q8 * 16) ^ ((uint32_t)(lrow & 7) << 4));
        char* img = (char*)g_x2 + ((size_t)(tile * 4 + kb)) * 32768 + off;
        *(uint4*)img           = make_uint4(h01, h23, h45, h67);
        *(uint4*)(img + 16384) = make_uint4(l01, l23, l45, l67);
        return;
    }

    if (blockIdx.x >= 16) {
        // ---- prep_w ----
        const int gi = ((blockIdx.x - 16) * 512 + tid) * 4;
        float4 v = *(const float4*)(w_conv + gi);
        const int d = gi >> 8, k = gi & 255;
        uint32_t h01, h23, l01, l23;
        split4(v, h01, h23, l01, l23);
        const int c = d & 255, r = d >> 8;
        const int nh = c >> 7;
        const int lrow = (c & 127) + (r << 7);
        const int kb = k >> 6, kc = k & 63;
        const uint32_t off = (uint32_t)lrow * 128 + (((uint32_t)kc * 2) ^ ((uint32_t)(lrow & 7) << 4));
        char* basehi = (char*)g_w3 + (size_t)(kb * 4 + nh) * 32768 + off;
        char* baselo = (char*)g_w3 + (size_t)(kb * 4 + 2 + nh) * 32768 + off;
        *(uint2*)basehi = make_uint2(h01, h23);
        *(uint2*)baselo = make_uint2(l01, l23);
        return;
    }

    // ---- attention (conv inline) ----
    const int b = blockIdx.x;
    __shared__ float xs0[CIN], xs1[CIN];
    __shared__ float h0[DW], h1[DW];
    __shared__ float gap0[CH_], gap1[CH_];
    __shared__ float g0[IN_], g1[IN_], gd[IN_];

    if (tid < CIN) {
        xs0[tid] = x[(b * N_ + 0)    * CIN + tid];
        xs1[tid] = x[(b * N_ + 1024) * CIN + tid];
    }
    __syncthreads();

    {
        const int d = tid;
        const float4* w = (const float4*)(w_conv + d * CIN);
        float s0 = 0.f, s1 = 0.f;
        #pragma unroll 8
        for (int k4 = 0; k4 < CIN / 4; k4++) {
            float4 wv = w[k4];
            float4 x0 = ((const float4*)xs0)[k4];
            float4 x1 = ((const float4*)xs1)[k4];
            s0 += wv.x * x0.x + wv.y * x0.y + wv.z * x0.z + wv.w * x0.w;
            s1 += wv.x * x1.x + wv.y * x1.y + wv.z * x1.z + wv.w * x1.w;
        }
        const float bb = b_conv[d];
        h0[d] = fmaxf(s0 + bb, 0.f);
        h1[d] = fmaxf(s1 + bb, 0.f);
    }
    __syncthreads();

    if (tid < CH_) {
        gap0[tid] = h0[tid] + h0[tid + CH_];
        gap1[tid] = h1[tid] + h1[tid + CH_];
    }
    __syncthreads();

    if (tid < 256) {
        const int i = tid & 127;
        const float* gp = (tid < 128) ? gap0 : gap1;
        const float4* w = (const float4*)(w_fc1 + i * CH_);
        float s = 0.f;
        #pragma unroll 8
        for (int k4 = 0; k4 < CH_ / 4; k4++) {
            float4 wv = w[k4];
            float4 gv = ((const float4*)gp)[k4];
            s += wv.x * gv.x + wv.y * gv.y + wv.z * gv.z + wv.w * gv.w;
        }
        s = fmaxf(s + b_fc1[i], 0.f);
        if (tid < 128) g0[i] = s; else g1[i] = s;
    }
    __syncthreads();
    if (tid < IN_) gd[tid] = g0[tid] - g1[tid];
    __syncthreads();

    {
        const int d = tid;
        const float4* w = (const float4*)(w_fc2 + d * IN_);
        float s = 0.f;
        #pragma unroll 8
        for (int k4 = 0; k4 < IN_ / 4; k4++) {
            float4 wv = w[k4];
            float4 gv = ((const float4*)gd)[k4];
            s += wv.x * gv.x + wv.y * gv.y + wv.z * gv.z + wv.w * gv.w;
        }
        g_attw[b * DW + d] = 1.f / (1.f + expf(-s));
    }
}

// ---------------------------------------------------------------------------
// GEMM: persistent cg1 tcgen05 — round-13 structure (h ping-pong TMEM with
// EPIF(h)/MDN(h) epilogue overlap, fully async A) with rebalanced SMEM:
// A = 2-stage 32KB double-buffer (reloaded per half, L2-hot reread),
// W = 5-stage 32KB ring (160KB buffered ~= 3750 cyc of W consumption ->
// TMA latency fully covered). Warp0 MMA, warp1 W-prod, warps2-9 epilogue,
// warp10 A-prod. SMEM total 225KB.
// ---------------------------------------------------------------------------
#define A_OFF   1024
#define W_OFF   (1024 + 2 * 32768)
#define SMEM_TOTAL (1024 + 2 * 32768 + 5 * 32768)

__global__ __launch_bounds__(352, 1)
void gemm_kernel(const float* __restrict__ x,
                 const float* __restrict__ w_conv,
                 const float* __restrict__ b_conv,
                 float* __restrict__ out)
{
    extern __shared__ __align__(1024) char smem[];
    const int tid = threadIdx.x;

#if USE_TCGEN05
    const uint32_t sb = smem_u32(smem);
    const int wid = tid >> 5, lid = tid & 31;
    const int bid = blockIdx.x;
    const int ntiles = (NTILES_TOTAL - bid + GRID_GEMM - 1) / GRID_GEMM;

    #define WF(s)   (sb + 8   + (s) * 8)   // 5 slots
    #define WE(s)   (sb + 48  + (s) * 8)   // 5 slots
    #define AF(q)   (sb + 88  + (q) * 8)   // 2 slots
    #define AR(q)   (sb + 104 + (q) * 8)   // 2 slots
    #define MDN(h)  (sb + 120 + (h) * 8)
    #define EPIF(h) (sb + 136 + (h) * 8)

    if (wid == 0) TCGEN05_ALLOC(sb, 512);
    if (tid == 0) {
        #pragma unroll
        for (int s = 0; s < 5; s++) { MBARRIER_INIT(WF(s), 1); MBARRIER_INIT(WE(s), 1); }
        MBARRIER_INIT(AF(0), 1); MBARRIER_INIT(AF(1), 1);
        MBARRIER_INIT(AR(0), 1); MBARRIER_INIT(AR(1), 1);
        MBARRIER_INIT(MDN(0), 1);  MBARRIER_INIT(MDN(1), 1);
        MBARRIER_INIT(EPIF(0), 256); MBARRIER_INIT(EPIF(1), 256);
    }
    __syncthreads();
    uint32_t tmem;
    asm volatile("ld.shared.b32 %0, [%1];" : "=r"(tmem) : "r"(sb));

    if (wid == 0) {
        // ================= MMA warp =================
        if (elect_one()) {
            int wst = 0, achunk = 0;
            int wfph[5] = {0, 0, 0, 0, 0};
            int afph[2] = {0, 0};
            for (int tt = 0; tt < ntiles; tt++) {
                #pragma unroll 1
                for (int h = 0; h < 2; h++) {
                    if (tt > 0) MBARRIER_WAIT_PARITY(EPIF(h), (tt - 1) & 1);
                    const uint32_t dst = tmem + h * 256;
                    #pragma unroll 1
                    for (int kb = 0; kb < 4; kb++) {
                        const int q = achunk & 1;
                        MBARRIER_WAIT_PARITY(AF(q), afph[q]); afph[q] ^= 1;
                        const uint32_t ab = sb + A_OFF + q * 32768;
                        const uint64_t ahi = MAKE_SMEM_DESC(ab);
                        const uint64_t alo = MAKE_SMEM_DESC(ab + 16384);
                        // --- whi chunk: (ahi + alo) * whi ---
                        MBARRIER_WAIT_PARITY(WF(wst), wfph[wst]); wfph[wst] ^= 1;
                        {
                            const uint64_t wd = MAKE_SMEM_DESC(sb + W_OFF + wst * 32768);
                            #pragma unroll
                            for (int k = 0; k < 4; k++)
                                mma_f16_ss(dst, ahi + k * 2, wd + k * 2, IDESC, !(kb == 0 && k == 0));
                            #pragma unroll
                            for (int k = 0; k < 4; k++)
                                mma_f16_ss(dst, alo + k * 2, wd + k * 2, IDESC, true);
                            TCGEN05_COMMIT(WE(wst));
                        }
                        wst = (wst == 4) ? 0 : wst + 1;
                        // --- wlo chunk: ahi * wlo ---
                        MBARRIER_WAIT_PARITY(WF(wst), wfph[wst]); wfph[wst] ^= 1;
                        {
                            const uint64_t wd = MAKE_SMEM_DESC(sb + W_OFF + wst * 32768);
                            #pragma unroll
                            for (int k = 0; k < 4; k++)
                                mma_f16_ss(dst, ahi + k * 2, wd + k * 2, IDESC, true);
                            TCGEN05_COMMIT(WE(wst));
                        }
                        wst = (wst == 4) ? 0 : wst + 1;
                        TCGEN05_COMMIT(AR(q));      // A buffer q free
                        achunk++;
                    }
                    TCGEN05_COMMIT(MDN(h));          // half h final
                }
            }
        }
    } else if (wid == 1) {
        // ================= W producer: continuous 5-stage ring ==============
        if (elect_one()) {
            const char* wsrc = (const char*)g_w3;
            int wst = 0, wc = 0;
            int weph[5] = {0, 0, 0, 0, 0};
            for (int tt = 0; tt < ntiles; tt++)
                #pragma unroll 1
                for (int h = 0; h < 2; h++)
                    #pragma unroll 1
                    for (int kb = 0; kb < 4; kb++)
                        #pragma unroll
                        for (int isl = 0; isl < 2; isl++) {
                            if (wc >= 5) { MBARRIER_WAIT_PARITY(WE(wst), weph[wst]); weph[wst] ^= 1; }
                            MBARRIER_EXPECT_TX(WF(wst), 32768);
                            BULK_G2S(sb + W_OFF + wst * 32768,
                                     wsrc + (size_t)(kb * 4 + isl * 2 + h) * 32768,
                                     32768, WF(wst));
                            wst = (wst == 4) ? 0 : wst + 1;
                            wc++;
                        }
        }
    } else if (wid <= 9) {
        // ================= Epilogue (8 warps, 256 threads) ==================
        const int cg = (wid <= 5) ? 0 : 1;       // 64-channel sub-group
        const int m  = (wid & 3) * 32 + lid;     // own TMEM subpartition rows
        for (int tt = 0; tt < ntiles; tt++) {
            const int m0 = (bid + GRID_GEMM * tt) * 128;
            const int bb = m0 >> 12;
            const int n  = (m0 & (N_ - 1)) + m;
            float* __restrict__ orow = out + ((size_t)n * B_ + bb) * CH_;
            const float* __restrict__ aw = g_attw + bb * DW;
            #pragma unroll 1
            for (int h = 0; h < 2; h++) {
                MBARRIER_WAIT_PARITY(MDN(h), tt & 1);
                TCGEN05_FENCE_AFTER();
                #pragma unroll
                for (int cc = 0; cc < 2; cc++) {
                    uint32_t hr0[32], hr1[32];
                    TCGEN05_LD_X32(hr0, tmem + h * 256 + cg * 64 + cc * 32);        // radix 0
                    TCGEN05_LD_X32(hr1, tmem + h * 256 + 128 + cg * 64 + cc * 32);  // radix 1
                    TCGEN05_WAIT_LD();
                    #pragma unroll
                    for (int qq = 0; qq < 8; qq++) {
                        const int ch = h * 128 + cg * 64 + cc * 32 + qq * 4;
                        float4 b0 = *(const float4*)&b_conv[ch];
                        float4 b1 = *(const float4*)&b_conv[256 + ch];
                        float4 a0 = *(const float4*)&aw[ch];
                        float4 a1 = *(const float4*)&aw[256 + ch];
                        float4 o;
                        o.x = a0.x * fmaxf(__uint_as_float(hr0[qq*4+0]) + b0.x, 0.f)
                            + a1.x * fmaxf(__uint_as_float(hr1[qq*4+0]) + b1.x, 0.f);
                        o.y = a0.y * fmaxf(__uint_as_float(hr0[qq*4+1]) + b0.y, 0.f)
                            + a1.y * fmaxf(__uint_as_float(hr1[qq*4+1]) + b1.y, 0.f);
                        o.z = a0.z * fmaxf(__uint_as_float(hr0[qq*4+2]) + b0.z, 0.f)
                            + a1.z * fmaxf(__uint_as_float(hr1[qq*4+2]) + b1.z, 0.f);
                        o.w = a0.w * fmaxf(__uint_as_float(hr0[qq*4+3]) + b0.w, 0.f)
                            + a1.w * fmaxf(__uint_as_float(hr1[qq*4+3]) + b1.w, 0.f);
                        *(float4*)(orow + ch) = o;
                    }
                }
                MBARRIER_ARRIVE(EPIF(h));   // TMEM half h free
            }
        }
    } else if (wid == 10) {
        // ================= A producer: 2-stage double-buffer, reload per half
        if (elect_one()) {
            int arph[2] = {0, 0};
            int achunk = 0;
            for (int tt = 0; tt < ntiles; tt++) {
                const int tile = bid + GRID_GEMM * tt;
                #pragma unroll 1
                for (int h = 0; h < 2; h++) {
                    #pragma unroll 1
                    for (int kb = 0; kb < 4; kb++) {
                        const int q = achunk & 1;
                        if (achunk >= 2) { MBARRIER_WAIT_PARITY(AR(q), arph[q]); arph[q] ^= 1; }
                        MBARRIER_EXPECT_TX(AF(q), 32768);
                        BULK_G2S(sb + A_OFF + q * 32768,
                                 (const char*)g_x2 + (size_t)(tile * 4 + kb) * 32768,
                                 32768, AF(q));
                        achunk++;
                    }
                }
            }
        }
    }

    __syncthreads();
    if (wid == 0) { TCGEN05_DEALLOC(tmem, 512); TCGEN05_RELINQ(); }

#else  // ------------------- naive fallback (plain sm_103; dead code) -------
    const int total = B_ * N_;
    for (int row = blockIdx.x; row < total; row += gridDim.x) {
        const int b = row >> 12, n = row & (N_ - 1);
        const float* xr = x + (size_t)row * CIN;
        for (int ch = tid; ch < CH_; ch += blockDim.x) {
            float s0 = 0.f, s1 = 0.f;
            for (int k = 0; k < CIN; k++) {
                const float xv = xr[k];
                s0 += xv * w_conv[(size_t)ch * CIN + k];
                s1 += xv * w_conv[(size_t)(256 + ch) * CIN + k];
            }
            const float h0v = fmaxf(s0 + b_conv[ch], 0.f);
            const float h1v = fmaxf(s1 + b_conv[256 + ch], 0.f);
            out[((size_t)n * B_ + b) * CH_ + ch] =
                g_attw[b * DW + ch] * h0v + g_attw[b * DW + 256 + ch] * h1v;
        }
    }
#endif
}

extern "C" void kernel_launch(void* const* d_in, const int* in_sizes, int n_in,
                              void* d_out, int out_size) {
    const float* x      = (const float*)d_in[0];
    const float* w_conv = (const float*)d_in[1];
    const float* b_conv = (const float*)d_in[2];
    const float* w_fc1  = (const float*)d_in[3];
    const float* b_fc1  = (const float*)d_in[4];
    const float* w_fc2  = (const float*)d_in[5];
    // d_in[6] = b_fc2: cancels in the softmax-pair difference, unused.
    float* out = (float*)d_out;

    cudaFuncSetAttribute(gemm_kernel, cudaFuncAttributeMaxDynamicSharedMemorySize, SMEM_TOTAL);

    setup_kernel<<<16 + 64 + 4096, 512>>>(x, w_conv, b_conv, w_fc1, b_fc1, w_fc2);
    gemm_kernel<<<GRID_GEMM, 352, SMEM_TOTAL>>>(x, w_conv, b_conv, out);
}

// round 17
// speedup vs baseline: 1.1220x; 1.0097x over previous
#include <cuda_runtime.h>
#include <cuda_bf16.h>
#include <cstdint>
#include <math.h>

#define B_    16
#define N_    4096
#define CIN   256
#define CH_   256
#define DW    512
#define IN_   128
#define NTILES_TOTAL 512
#define GRID_GEMM 148

// tcgen05 asm only compiles under an 'a'-suffixed target pass.
#if defined(__CUDA_ARCH_FEAT_SM103_ALL) || defined(__CUDA_ARCH_FEAT_SM100_ALL) || defined(__CUDA_ARCH_FEAT_SM101_ALL)
#define USE_TCGEN05 1
#else
#define USE_TCGEN05 0
#endif

// -------------------- device scratch --------------------
__device__ float g_attw[B_ * DW];
// W: 16 pre-swizzled 32KB images (256 rows x 128B, SW128 baked in).
// image j = kb*4 + islo*2 + h.  Row perm: w_conv row d (c=d&255, r=d>>8) ->
// h=c>>7, lrow=(c&127)+r*128.  D col (N=256 MMA for channel-half h) = lrow.
__device__ __nv_bfloat16 g_w3[16 * 256 * 64];
// A: pre-split, pre-swizzled SMEM-ready images: [tile128][kb][hi 16KB|lo 16KB].
__device__ __nv_bfloat16 g_x2[(size_t)NTILES_TOTAL * 4 * 16384];

// -------------------- PTX helpers --------------------
__device__ __forceinline__ uint32_t smem_u32(const void* p) {
    uint32_t a;
    asm("{ .reg .u64 t; cvta.to.shared.u64 t, %1; cvt.u32.u64 %0, t; }" : "=r"(a) : "l"(p));
    return a;
}
__device__ __forceinline__ uint32_t elect_one() {
    uint32_t pred;
    asm volatile("{\n\t.reg .pred p;\n\telect.sync _|p, 0xFFFFFFFF;\n\tselp.b32 %0, 1, 0, p;\n\t}" : "=r"(pred));
    return pred;
}
#define TCGEN05_ALLOC(sa, n) \
    asm volatile("tcgen05.alloc.cta_group::1.sync.aligned.shared::cta.b32 [%0], %1;" :: "r"((uint32_t)(sa)), "r"((uint32_t)(n)) : "memory")
#define TCGEN05_DEALLOC(t, n) \
    asm volatile("tcgen05.dealloc.cta_group::1.sync.aligned.b32 %0, %1;" :: "r"(t), "r"((uint32_t)(n)))
#define TCGEN05_RELINQ() \
    asm volatile("tcgen05.relinquish_alloc_permit.cta_group::1.sync.aligned;")
#define TCGEN05_COMMIT(mb) \
    asm volatile("tcgen05.commit.cta_group::1.mbarrier::arrive::one.shared::cluster.b64 [%0];" :: "r"((uint32_t)(mb)) : "memory")
#define TCGEN05_WAIT_LD() asm volatile("tcgen05.wait::ld.sync.aligned;" ::: "memory")
#define TCGEN05_FENCE_AFTER() asm volatile("tcgen05.fence::after_thread_sync;" ::: "memory")
#define MBARRIER_INIT(mb, cnt) \
    asm volatile("mbarrier.init.shared.b64 [%0], %1;" :: "r"((uint32_t)(mb)), "r"((uint32_t)(cnt)) : "memory")
#define MBARRIER_ARRIVE(mb) \
    asm volatile("mbarrier.arrive.shared.b64 _, [%0];" :: "r"((uint32_t)(mb)) : "memory")
#define MBARRIER_EXPECT_TX(mb, bytes) \
    asm volatile("mbarrier.arrive.expect_tx.shared.b64 _, [%0], %1;" :: "r"((uint32_t)(mb)), "r"((uint32_t)(bytes)) : "memory")
#define MBARRIER_WAIT_PARITY(mb, ph) do { \
    uint32_t _m = (uint32_t)(mb), _p = (uint32_t)(ph), _d; \
    asm volatile("{\n\t.reg .pred p;\n\tmbarrier.try_wait.parity.acquire.cta.shared::cta.b64 p, [%1], %2;\n\tselp.b32 %0, 1, 0, p;\n\t}" \
        : "=r"(_d) : "r"(_m), "r"(_p) : "memory"); \
    if (!_d) { \
        asm volatile("{\n\t.reg .pred P1;\n\tWL_%=:\n\tmbarrier.try_wait.parity.acquire.cta.shared::cta.b64 P1, [%0], %1, 0x989680;\n\t@P1 bra.uni WD_%=;\n\tbra.uni WL_%=;\n\tWD_%=:\n\t}" \
            :: "r"(_m), "r"(_p) : "memory"); \
    } \
} while (0)
#define BULK_G2S(dst, src, bytes, mb) \
    asm volatile("cp.async.bulk.shared::cta.global.mbarrier::complete_tx::bytes [%0], [%1], %2, [%3];" \
        :: "r"((uint32_t)(dst)), "l"(src), "r"((uint32_t)(bytes)), "r"((uint32_t)(mb)) : "memory")
#define TCGEN05_LD_X32(r, ta) \
    asm volatile("tcgen05.ld.sync.aligned.32x32b.x32.b32 " \
        "{%0,%1,%2,%3,%4,%5,%6,%7,%8,%9,%10,%11,%12,%13,%14,%15," \
        "%16,%17,%18,%19,%20,%21,%22,%23,%24,%25,%26,%27,%28,%29,%30,%31}, [%32];" \
        : "=r"((r)[0]),"=r"((r)[1]),"=r"((r)[2]),"=r"((r)[3]),"=r"((r)[4]),"=r"((r)[5]),"=r"((r)[6]),"=r"((r)[7]), \
          "=r"((r)[8]),"=r"((r)[9]),"=r"((r)[10]),"=r"((r)[11]),"=r"((r)[12]),"=r"((r)[13]),"=r"((r)[14]),"=r"((r)[15]), \
          "=r"((r)[16]),"=r"((r)[17]),"=r"((r)[18]),"=r"((r)[19]),"=r"((r)[20]),"=r"((r)[21]),"=r"((r)[22]),"=r"((r)[23]), \
          "=r"((r)[24]),"=r"((r)[25]),"=r"((r)[26]),"=r"((r)[27]),"=r"((r)[28]),"=r"((r)[29]),"=r"((r)[30]),"=r"((r)[31]) \
        : "r"(ta))

static constexpr uint64_t SMEM_DESC_BASE_SW128 =
    (uint64_t(2) << 61) | (uint64_t(1) << 46) | (uint64_t(64) << 32) | (uint64_t(1) << 16);
#define MAKE_SMEM_DESC(a) (SMEM_DESC_BASE_SW128 | ((uint64_t)((a) >> 4) & 0x3FFF))

#if USE_TCGEN05
// SS-mode cg1 bf16 MMA: D[128,256] += A[128,16] * B[256,16]^T
__device__ __forceinline__ void mma_f16_ss(uint32_t d, uint64_t ad, uint64_t bd, uint32_t idesc, bool acc) {
    uint32_t en = acc ? 1u : 0u;
    asm volatile(
        "{\n\t.reg .pred p;\n\tsetp.ne.u32 p, %5, 0;\n\t"
        "tcgen05.mma.cta_group::1.kind::f16 [%0], %1, %2, %3, {%4, %4, %4, %4}, p;\n\t}"
        :: "r"(d), "l"(ad), "l"(bd), "r"(idesc), "r"(0u), "r"(en) : "memory");
}
#endif
// idesc: F32 accum, BF16 x BF16, M=128, N=256
static constexpr uint32_t IDESC =
    (1u << 4) | (1u << 7) | (1u << 10) | ((256u / 8u) << 17) | ((128u / 16u) << 24);

// fp32 -> bf16 hi/lo split, packed pairs
__device__ __forceinline__ void split4(const float4 v, uint32_t& h01, uint32_t& h23,
                                       uint32_t& l01, uint32_t& l23) {
    __nv_bfloat162 h0 = __floats2bfloat162_rn(v.x, v.y);
    __nv_bfloat162 h1 = __floats2bfloat162_rn(v.z, v.w);
    __nv_bfloat162 l0 = __floats2bfloat162_rn(v.x - __bfloat162float(h0.x),
                                              v.y - __bfloat162float(h0.y));
    __nv_bfloat162 l1 = __floats2bfloat162_rn(v.z - __bfloat162float(h1.x),
                                              v.w - __bfloat162float(h1.y));
    h01 = *(uint32_t*)&h0; h23 = *(uint32_t*)&h1;
    l01 = *(uint32_t*)&l0; l23 = *(uint32_t*)&l1;
}

// ---------------------------------------------------------------------------
// Setup (single launch, 4176 blocks x 512) — unchanged from round 16:
//   blocks 0..15    attention chain; 16..79 prep_w; 80..4175 prep_x.
// ---------------------------------------------------------------------------
__global__ __launch_bounds__(512) void setup_kernel(
    const float* __restrict__ x,
    const float* __restrict__ w_conv,
    const float* __restrict__ b_conv,
    const float* __restrict__ w_fc1,
    const float* __restrict__ b_fc1,
    const float* __restrict__ w_fc2)
{
    const int tid = threadIdx.x;

    if (blockIdx.x >= 80) {
        // ---- prep_x: 8 floats/thread, uint4 hi + uint4 lo ----
        const size_t fi = ((size_t)(blockIdx.x - 80) * 512 + tid) * 8;
        float4 v0 = *(const float4*)(x + fi);
        float4 v1 = *(const float4*)(x + fi + 4);
        uint32_t h01, h23, l01, l23, h45, h67, l45, l67;
        split4(v0, h01, h23, l01, l23);
        split4(v1, h45, h67, l45, l67);
        const int row  = (int)(fi >> 8);
        const int k    = (int)(fi & 255);
        const int tile = row >> 7, lrow = row & 127;
        const int kb   = k >> 6,  q8   = (k & 63) >> 3;
        const uint32_t off = (uint32_t)lrow * 128 + (((uint32_t)q8 * 16) ^ ((uint32_t)(lrow & 7) << 4));
        char* img = (char*)g_x2 + ((size_t)(tile * 4 + kb)) * 32768 + off;
        *(uint4*)img           = make_uint4(h01, h23, h45, h67);
        *(uint4*)(img + 16384) = make_uint4(l01, l23, l45, l67);
        return;
    }

    if (blockIdx.x >= 16) {
        // ---- prep_w ----
        const int gi = ((blockIdx.x - 16) * 512 + tid) * 4;
        float4 v = *(const float4*)(w_conv + gi);
        const int d = gi >> 8, k = gi & 255;
        uint32_t h01, h23, l01, l23;
        split4(v, h01, h23, l01, l23);
        const int c = d & 255, r = d >> 8;
        const int nh = c >> 7;
        const int lrow = (c & 127) + (r << 7);
        const int kb = k >> 6, kc = k & 63;
        const uint32_t off = (uint32_t)lrow * 128 + (((uint32_t)kc * 2) ^ ((uint32_t)(lrow & 7) << 4));
        char* basehi = (char*)g_w3 + (size_t)(kb * 4 + nh) * 32768 + off;
        char* baselo = (char*)g_w3 + (size_t)(kb * 4 + 2 + nh) * 32768 + off;
        *(uint2*)basehi = make_uint2(h01, h23);
        *(uint2*)baselo = make_uint2(l01, l23);
        return;
    }

    // ---- attention (conv inline) ----
    const int b = blockIdx.x;
    __shared__ float xs0[CIN], xs1[CIN];
    __shared__ float h0[DW], h1[DW];
    __shared__ float gap0[CH_], gap1[CH_];
    __shared__ float g0[IN_], g1[IN_], gd[IN_];

    if (tid < CIN) {
        xs0[tid] = x[(b * N_ + 0)    * CIN + tid];
        xs1[tid] = x[(b * N_ + 1024) * CIN + tid];
    }
    __syncthreads();

    {
        const int d = tid;
        const float4* w = (const float4*)(w_conv + d * CIN);
        float s0 = 0.f, s1 = 0.f;
        #pragma unroll 8
        for (int k4 = 0; k4 < CIN / 4; k4++) {
            float4 wv = w[k4];
            float4 x0 = ((const float4*)xs0)[k4];
            float4 x1 = ((const float4*)xs1)[k4];
            s0 += wv.x * x0.x + wv.y * x0.y + wv.z * x0.z + wv.w * x0.w;
            s1 += wv.x * x1.x + wv.y * x1.y + wv.z * x1.z + wv.w * x1.w;
        }
        const float bb = b_conv[d];
        h0[d] = fmaxf(s0 + bb, 0.f);
        h1[d] = fmaxf(s1 + bb, 0.f);
    }
    __syncthreads();

    if (tid < CH_) {
        gap0[tid] = h0[tid] + h0[tid + CH_];
        gap1[tid] = h1[tid] + h1[tid + CH_];
    }
    __syncthreads();

    if (tid < 256) {
        const int i = tid & 127;
        const float* gp = (tid < 128) ? gap0 : gap1;
        const float4* w = (const float4*)(w_fc1 + i * CH_);
        float s = 0.f;
        #pragma unroll 8
        for (int k4 = 0; k4 < CH_ / 4; k4++) {
            float4 wv = w[k4];
            float4 gv = ((const float4*)gp)[k4];
            s += wv.x * gv.x + wv.y * gv.y + wv.z * gv.z + wv.w * gv.w;
        }
        s = fmaxf(s + b_fc1[i], 0.f);
        if (tid < 128) g0[i] = s; else g1[i] = s;
    }
    __syncthreads();
    if (tid < IN_) gd[tid] = g0[tid] - g1[tid];
    __syncthreads();

    {
        const int d = tid;
        const float4* w = (const float4*)(w_fc2 + d * IN_);
        float s = 0.f;
        #pragma unroll 8
        for (int k4 = 0; k4 < IN_ / 4; k4++) {
            float4 wv = w[k4];
            float4 gv = ((const float4*)gd)[k4];
            s += wv.x * gv.x + wv.y * gv.y + wv.z * gv.z + wv.w * gv.w;
        }
        g_attw[b * DW + d] = 1.f / (1.f + expf(-s));
    }
}

// ---------------------------------------------------------------------------
// GEMM: round-16 structure with WARP ROLES PERMUTED FOR ARBITER PRIORITY
// (hi-wid-first SMSP arbitration): MMA warp = wid 10 (top priority on its
// SMSP), W producer = wid 9, A producer = wid 8, epilogue = wids 0-7.
// A = 2-stage 32KB double-buffer (reload per half), W = 5-stage 32KB ring.
// ---------------------------------------------------------------------------
#define A_OFF   1024
#define W_OFF   (1024 + 2 * 32768)
#define SMEM_TOTAL (1024 + 2 * 32768 + 5 * 32768)

__global__ __launch_bounds__(352, 1)
void gemm_kernel(const float* __restrict__ x,
                 const float* __restrict__ w_conv,
                 const float* __restrict__ b_conv,
                 float* __restrict__ out)
{
    extern __shared__ __align__(1024) char smem[];
    const int tid = threadIdx.x;

#if USE_TCGEN05
    const uint32_t sb = smem_u32(smem);
    const int wid = tid >> 5, lid = tid & 31;
    const int bid = blockIdx.x;
    const int ntiles = (NTILES_TOTAL - bid + GRID_GEMM - 1) / GRID_GEMM;

    #define WF(s)   (sb + 8   + (s) * 8)   // 5 slots
    #define WE(s)   (sb + 48  + (s) * 8)   // 5 slots
    #define AF(q)   (sb + 88  + (q) * 8)   // 2 slots
    #define AR(q)   (sb + 104 + (q) * 8)   // 2 slots
    #define MDN(h)  (sb + 120 + (h) * 8)
    #define EPIF(h) (sb + 136 + (h) * 8)

    if (wid == 10) TCGEN05_ALLOC(sb, 512);
    if (tid == 0) {
        #pragma unroll
        for (int s = 0; s < 5; s++) { MBARRIER_INIT(WF(s), 1); MBARRIER_INIT(WE(s), 1); }
        MBARRIER_INIT(AF(0), 1); MBARRIER_INIT(AF(1), 1);
        MBARRIER_INIT(AR(0), 1); MBARRIER_INIT(AR(1), 1);
        MBARRIER_INIT(MDN(0), 1);  MBARRIER_INIT(MDN(1), 1);
        MBARRIER_INIT(EPIF(0), 256); MBARRIER_INIT(EPIF(1), 256);
    }
    __syncthreads();
    uint32_t tmem;
    asm volatile("ld.shared.b32 %0, [%1];" : "=r"(tmem) : "r"(sb));

    if (wid == 10) {
        // ================= MMA warp (top arbiter priority) =================
        if (elect_one()) {
            int wst = 0, achunk = 0;
            int wfph[5] = {0, 0, 0, 0, 0};
            int afph[2] = {0, 0};
            for (int tt = 0; tt < ntiles; tt++) {
                #pragma unroll 1
                for (int h = 0; h < 2; h++) {
                    if (tt > 0) MBARRIER_WAIT_PARITY(EPIF(h), (tt - 1) & 1);
                    const uint32_t dst = tmem + h * 256;
                    #pragma unroll 1
                    for (int kb = 0; kb < 4; kb++) {
                        const int q = achunk & 1;
                        MBARRIER_WAIT_PARITY(AF(q), afph[q]); afph[q] ^= 1;
                        const uint32_t ab = sb + A_OFF + q * 32768;
                        const uint64_t ahi = MAKE_SMEM_DESC(ab);
                        const uint64_t alo = MAKE_SMEM_DESC(ab + 16384);
                        // --- whi chunk: (ahi + alo) * whi ---
                        MBARRIER_WAIT_PARITY(WF(wst), wfph[wst]); wfph[wst] ^= 1;
                        {
                            const uint64_t wd = MAKE_SMEM_DESC(sb + W_OFF + wst * 32768);
                            #pragma unroll
                            for (int k = 0; k < 4; k++)
                                mma_f16_ss(dst, ahi + k * 2, wd + k * 2, IDESC, !(kb == 0 && k == 0));
                            #pragma unroll
                            for (int k = 0; k < 4; k++)
                                mma_f16_ss(dst, alo + k * 2, wd + k * 2, IDESC, true);
                            TCGEN05_COMMIT(WE(wst));
                        }
                        wst = (wst == 4) ? 0 : wst + 1;
                        // --- wlo chunk: ahi * wlo ---
                        MBARRIER_WAIT_PARITY(WF(wst), wfph[wst]); wfph[wst] ^= 1;
                        {
                            const uint64_t wd = MAKE_SMEM_DESC(sb + W_OFF + wst * 32768);
                            #pragma unroll
                            for (int k = 0; k < 4; k++)
                                mma_f16_ss(dst, ahi + k * 2, wd + k * 2, IDESC, true);
                            TCGEN05_COMMIT(WE(wst));
                        }
                        wst = (wst == 4) ? 0 : wst + 1;
                        TCGEN05_COMMIT(AR(q));      // A buffer q free
                        achunk++;
                    }
                    TCGEN05_COMMIT(MDN(h));          // half h final
                }
            }
        }
    } else if (wid == 9) {
        // ================= W producer: continuous 5-stage ring ==============
        if (elect_one()) {
            const char* wsrc = (const char*)g_w3;
            int wst = 0, wc = 0;
            int weph[5] = {0, 0, 0, 0, 0};
            for (int tt = 0; tt < ntiles; tt++)
                #pragma unroll 1
                for (int h = 0; h < 2; h++)
                    #pragma unroll 1
                    for (int kb = 0; kb < 4; kb++)
                        #pragma unroll
                        for (int isl = 0; isl < 2; isl++) {
                            if (wc >= 5) { MBARRIER_WAIT_PARITY(WE(wst), weph[wst]); weph[wst] ^= 1; }
                            MBARRIER_EXPECT_TX(WF(wst), 32768);
                            BULK_G2S(sb + W_OFF + wst * 32768,
                                     wsrc + (size_t)(kb * 4 + isl * 2 + h) * 32768,
                                     32768, WF(wst));
                            wst = (wst == 4) ? 0 : wst + 1;
                            wc++;
                        }
        }
    } else if (wid == 8) {
        // ================= A producer: 2-stage double-buffer, reload per half
        if (elect_one()) {
            int arph[2] = {0, 0};
            int achunk = 0;
            for (int tt = 0; tt < ntiles; tt++) {
                const int tile = bid + GRID_GEMM * tt;
                #pragma unroll 1
                for (int h = 0; h < 2; h++) {
                    #pragma unroll 1
                    for (int kb = 0; kb < 4; kb++) {
                        const int q = achunk & 1;
                        if (achunk >= 2) { MBARRIER_WAIT_PARITY(AR(q), arph[q]); arph[q] ^= 1; }
                        MBARRIER_EXPECT_TX(AF(q), 32768);
                        BULK_G2S(sb + A_OFF + q * 32768,
                                 (const char*)g_x2 + (size_t)(tile * 4 + kb) * 32768,
                                 32768, AF(q));
                        achunk++;
                    }
                }
            }
        }
    } else {
        // ================= Epilogue (8 warps, wids 0-7) =====================
        const int cg = (wid < 4) ? 0 : 1;        // 64-channel sub-group
        const int m  = (wid & 3) * 32 + lid;     // own TMEM subpartition rows
        for (int tt = 0; tt < ntiles; tt++) {
            const int m0 = (bid + GRID_GEMM * tt) * 128;
            const int bb = m0 >> 12;
            const int n  = (m0 & (N_ - 1)) + m;
            float* __restrict__ orow = out + ((size_t)n * B_ + bb) * CH_;
            const float* __restrict__ aw = g_attw + bb * DW;
            #pragma unroll 1
            for (int h = 0; h < 2; h++) {
                MBARRIER_WAIT_PARITY(MDN(h), tt & 1);
                TCGEN05_FENCE_AFTER();
                #pragma unroll
                for (int cc = 0; cc < 2; cc++) {
                    uint32_t hr0[32], hr1[32];
                    TCGEN05_LD_X32(hr0, tmem + h * 256 + cg * 64 + cc * 32);        // radix 0
                    TCGEN05_LD_X32(hr1, tmem + h * 256 + 128 + cg * 64 + cc * 32);  // radix 1
                    TCGEN05_WAIT_LD();
                    #pragma unroll
                    for (int qq = 0; qq < 8; qq++) {
                        const int ch = h * 128 + cg * 64 + cc * 32 + qq * 4;
                        float4 b0 = *(const float4*)&b_conv[ch];
                        float4 b1 = *(const float4*)&b_conv[256 + ch];
                        float4 a0 = *(const float4*)&aw[ch];
                        float4 a1 = *(const float4*)&aw[256 + ch];
                        float4 o;
                        o.x = a0.x * fmaxf(__uint_as_float(hr0[qq*4+0]) + b0.x, 0.f)
                            + a1.x * fmaxf(__uint_as_float(hr1[qq*4+0]) + b1.x, 0.f);
                        o.y = a0.y * fmaxf(__uint_as_float(hr0[qq*4+1]) + b0.y, 0.f)
                            + a1.y * fmaxf(__uint_as_float(hr1[qq*4+1]) + b1.y, 0.f);
                        o.z = a0.z * fmaxf(__uint_as_float(hr0[qq*4+2]) + b0.z, 0.f)
                            + a1.z * fmaxf(__uint_as_float(hr1[qq*4+2]) + b1.z, 0.f);
                        o.w = a0.w * fmaxf(__uint_as_float(hr0[qq*4+3]) + b0.w, 0.f)
                            + a1.w * fmaxf(__uint_as_float(hr1[qq*4+3]) + b1.w, 0.f);
                        *(float4*)(orow + ch) = o;
                    }
                }
                MBARRIER_ARRIVE(EPIF(h));   // TMEM half h free
            }
        }
    }

    __syncthreads();
    if (wid == 10) { TCGEN05_DEALLOC(tmem, 512); TCGEN05_RELINQ(); }

#else  // ------------------- naive fallback (plain sm_103; dead code) -------
    const int total = B_ * N_;
    for (int row = blockIdx.x; row < total; row += gridDim.x) {
        const int b = row >> 12, n = row & (N_ - 1);
        const float* xr = x + (size_t)row * CIN;
        for (int ch = tid; ch < CH_; ch += blockDim.x) {
            float s0 = 0.f, s1 = 0.f;
            for (int k = 0; k < CIN; k++) {
                const float xv = xr[k];
                s0 += xv * w_conv[(size_t)ch * CIN + k];
                s1 += xv * w_conv[(size_t)(256 + ch) * CIN + k];
            }
            const float h0v = fmaxf(s0 + b_conv[ch], 0.f);
            const float h1v = fmaxf(s1 + b_conv[256 + ch], 0.f);
            out[((size_t)n * B_ + b) * CH_ + ch] =
                g_attw[b * DW + ch] * h0v + g_attw[b * DW + 256 + ch] * h1v;
        }
    }
#endif
}

extern "C" void kernel_launch(void* const* d_in, const int* in_sizes, int n_in,
                              void* d_out, int out_size) {
    const float* x      = (const float*)d_in[0];
    const float* w_conv = (const float*)d_in[1];
    const float* b_conv = (const float*)d_in[2];
    const float* w_fc1  = (const float*)d_in[3];
    const float* b_fc1  = (const float*)d_in[4];
    const float* w_fc2  = (const float*)d_in[5];
    // d_in[6] = b_fc2: cancels in the softmax-pair difference, unused.
    float* out = (float*)d_out;

    cudaFuncSetAttribute(gemm_kernel, cudaFuncAttributeMaxDynamicSharedMemorySize, SMEM_TOTAL);

    setup_kernel<<<16 + 64 + 4096, 512>>>(x, w_conv, b_conv, w_fc1, b_fc1, w_fc2);
    gemm_kernel<<<GRID_GEMM, 352, SMEM_TOTAL>>>(x, w_conv, b_conv, out);
}